// round 4
// baseline (speedup 1.0000x reference)
#include <cuda_runtime.h>
#include <cstdint>

#define HIDDEN    1024
#define HEADS     16
#define HEAD_DIM  64
#define BATCH     4
#define SEQ       1024
#define ROWS      (BATCH*SEQ)        // 4096
#define BETA_F    0.9f
#define CLAMP_F   1.0f
#define STATE_CAP_F 10.0f
#define BK        16

// ---------------- scratch (static device arrays are allowed) ---------------
__device__ float g_q[ROWS*HIDDEN];
__device__ float g_k[ROWS*HIDDEN];
__device__ float g_v[ROWS*HIDDEN];
__device__ float g_o[ROWS*HIDDEN];
__device__ float g_state_scratch[BATCH*HEADS*HEAD_DIM*HEAD_DIM];

// ---------------------------------------------------------------------------
// GEMM: C[m,n] = sum_k A[m,k]*B[n,k] + bias[n]   (A:[M,K], B:[N,K] row-major)
// BM=BN=128, BK=16, 256 threads, 8x8 microtile, double-buffered smem,
// one __syncthreads per K-iteration.
// ---------------------------------------------------------------------------
__device__ __forceinline__ void gemm_nt_body(
    const float* __restrict__ A, const float* __restrict__ B,
    const float* __restrict__ bias, float* __restrict__ C,
    int N, int K, int m0, int n0)
{
    __shared__ float As[2][BK][128];   // 16 KB
    __shared__ float Bs[2][BK][128];   // 16 KB

    const int tid  = threadIdx.x;
    const int tx   = tid & 15;        // n microtile
    const int ty   = tid >> 4;        // m microtile
    const int lrow = tid >> 1;        // 0..127
    const int lcol = (tid & 1) * 8;   // 0 or 8

    const float* Aptr = A + (size_t)(m0 + lrow) * K + lcol;
    const float* Bptr = B + (size_t)(n0 + lrow) * K + lcol;

    float acc[8][8];
#pragma unroll
    for (int i = 0; i < 8; i++)
#pragma unroll
        for (int j = 0; j < 8; j++) acc[i][j] = 0.f;

    // prologue: stage 0
    float4 a0 = *(const float4*)(Aptr);
    float4 a1 = *(const float4*)(Aptr + 4);
    float4 b0 = *(const float4*)(Bptr);
    float4 b1 = *(const float4*)(Bptr + 4);
    As[0][lcol+0][lrow]=a0.x; As[0][lcol+1][lrow]=a0.y; As[0][lcol+2][lrow]=a0.z; As[0][lcol+3][lrow]=a0.w;
    As[0][lcol+4][lrow]=a1.x; As[0][lcol+5][lrow]=a1.y; As[0][lcol+6][lrow]=a1.z; As[0][lcol+7][lrow]=a1.w;
    Bs[0][lcol+0][lrow]=b0.x; Bs[0][lcol+1][lrow]=b0.y; Bs[0][lcol+2][lrow]=b0.z; Bs[0][lcol+3][lrow]=b0.w;
    Bs[0][lcol+4][lrow]=b1.x; Bs[0][lcol+5][lrow]=b1.y; Bs[0][lcol+6][lrow]=b1.z; Bs[0][lcol+7][lrow]=b1.w;
    __syncthreads();

    int buf = 0;
    for (int k0 = 0; k0 < K; k0 += BK) {
        const bool has_next = (k0 + BK) < K;
        if (has_next) {
            a0 = *(const float4*)(Aptr + k0 + BK);
            a1 = *(const float4*)(Aptr + k0 + BK + 4);
            b0 = *(const float4*)(Bptr + k0 + BK);
            b1 = *(const float4*)(Bptr + k0 + BK + 4);
        }
#pragma unroll
        for (int kk = 0; kk < BK; kk++) {
            float af[8], bf[8];
            *(float4*)(af)     = *(const float4*)&As[buf][kk][ty*8];
            *(float4*)(af + 4) = *(const float4*)&As[buf][kk][ty*8 + 4];
            *(float4*)(bf)     = *(const float4*)&Bs[buf][kk][tx*8];
            *(float4*)(bf + 4) = *(const float4*)&Bs[buf][kk][tx*8 + 4];
#pragma unroll
            for (int i = 0; i < 8; i++)
#pragma unroll
                for (int j = 0; j < 8; j++)
                    acc[i][j] += af[i] * bf[j];
        }
        if (has_next) {
            const int nb = buf ^ 1;
            As[nb][lcol+0][lrow]=a0.x; As[nb][lcol+1][lrow]=a0.y; As[nb][lcol+2][lrow]=a0.z; As[nb][lcol+3][lrow]=a0.w;
            As[nb][lcol+4][lrow]=a1.x; As[nb][lcol+5][lrow]=a1.y; As[nb][lcol+6][lrow]=a1.z; As[nb][lcol+7][lrow]=a1.w;
            Bs[nb][lcol+0][lrow]=b0.x; Bs[nb][lcol+1][lrow]=b0.y; Bs[nb][lcol+2][lrow]=b0.z; Bs[nb][lcol+3][lrow]=b0.w;
            Bs[nb][lcol+4][lrow]=b1.x; Bs[nb][lcol+5][lrow]=b1.y; Bs[nb][lcol+6][lrow]=b1.z; Bs[nb][lcol+7][lrow]=b1.w;
            __syncthreads();
            buf = nb;
        }
    }

    float bv[8];
#pragma unroll
    for (int j = 0; j < 8; j++) bv[j] = bias[n0 + tx*8 + j];

#pragma unroll
    for (int i = 0; i < 8; i++) {
        float* cp = C + (size_t)(m0 + ty*8 + i) * N + n0 + tx*8;
        float4 c0, c1;
        c0.x = acc[i][0]+bv[0]; c0.y = acc[i][1]+bv[1];
        c0.z = acc[i][2]+bv[2]; c0.w = acc[i][3]+bv[3];
        c1.x = acc[i][4]+bv[4]; c1.y = acc[i][5]+bv[5];
        c1.z = acc[i][6]+bv[6]; c1.w = acc[i][7]+bv[7];
        *(float4*)(cp)     = c0;
        *(float4*)(cp + 4) = c1;
    }
}

__global__ __launch_bounds__(256) void gemm_nt_kernel(
    const float* __restrict__ A, const float* __restrict__ B,
    const float* __restrict__ bias, float* __restrict__ C,
    int N, int K)
{
    gemm_nt_body(A, B, bias, C, N, K, blockIdx.y * 128, blockIdx.x * 128);
}

// One launch computes q, k, v (blockIdx.z selects the weight/output).
__global__ __launch_bounds__(256) void gemm_qkv_kernel(
    const float* __restrict__ X,
    const float* __restrict__ Wq, const float* __restrict__ bq,
    const float* __restrict__ Wk, const float* __restrict__ bk,
    const float* __restrict__ Wv, const float* __restrict__ bv)
{
    const float* W; const float* bias; float* out;
    if (blockIdx.z == 0)      { W = Wq; bias = bq; out = g_q; }
    else if (blockIdx.z == 1) { W = Wk; bias = bk; out = g_k; }
    else                      { W = Wv; bias = bv; out = g_v; }
    gemm_nt_body(X, W, bias, out, HIDDEN, HIDDEN,
                 blockIdx.y * 128, blockIdx.x * 128);
}

// ---------------------------------------------------------------------------
// L2 normalize q and k per head vector (64 contiguous floats).
// One warp per vector, 131072 vectors total -> 16384 blocks of 8 warps.
// ---------------------------------------------------------------------------
__global__ __launch_bounds__(256) void l2norm_kernel()
{
    const int warp = threadIdx.x >> 5;
    const int lane = threadIdx.x & 31;
    const long vid = (long)blockIdx.x * 8 + warp;   // 0 .. 131071
    const long NV  = (long)ROWS * HEADS;            // 65536
    float* base = (vid < NV) ? g_q : g_k;
    const long v = vid & (NV - 1);
    float* p = base + v * HEAD_DIM + lane * 2;
    float2 x = *(float2*)p;
    float ss = x.x * x.x + x.y * x.y;
#pragma unroll
    for (int off = 16; off; off >>= 1)
        ss += __shfl_xor_sync(0xffffffffu, ss, off);
    float n   = sqrtf(ss);
    float inv = 1.0f / fmaxf(n, 1e-12f);
    x.x *= inv; x.y *= inv;
    *(float2*)p = x;
}

// ---------------------------------------------------------------------------
// Sequential delta-rule scan, pipelined: 3 barriers/step.
// One 128-thread block per (b,h). Thread (t,g): t=column 0..63, g=row half.
// Owns S[g*32 .. g*32+31][t] in registers.
// Per step s:
//   phase1: delta from vold (computed last iter), rank-1 update, local max
//   barA  : __syncthreads_or for the state-cap test
//   phase2: optional 0.9 rescale; publish column to Ssh; stage k/q for s+1
//   barB
//   phase3: o_s partial (rows of Ssh x q_s) AND vold_{s+1} partial
//           (register columns x k_{s+1}) together
//   barC
//   phase4: combine partials, write o, roll buffers
// k/q live in double-buffered 64-float shared rows, read as float4.
// ---------------------------------------------------------------------------
__device__ __forceinline__ float clip1(float x) {
    return fminf(fmaxf(x, -CLAMP_F), CLAMP_F);
}

__global__ __launch_bounds__(128) void scan_kernel(float* __restrict__ state_out)
{
    __shared__ float Ssh[HEAD_DIM][HEAD_DIM + 1];
    __shared__ float ksh[2][HEAD_DIM];
    __shared__ float qsh[2][HEAD_DIM];
    __shared__ float pd[2][HEAD_DIM];    // v_old partials
    __shared__ float po[2][HEAD_DIM];    // o partials

    const int tid = threadIdx.x;
    const int t   = tid & 63;            // column
    const int g   = tid >> 6;            // row half
    const int rb  = g * 32;              // row base
    const int bh  = blockIdx.x;          // 0..63
    const size_t base = (size_t)(bh >> 4) * SEQ * HIDDEN
                      + (size_t)(bh & 15) * HEAD_DIM;

    float Scol[32];
#pragma unroll
    for (int i = 0; i < 32; i++) Scol[i] = 0.f;

    // stage step 0: threads g=0 load k, g=1 load q (one element each)
    if (g == 0) ksh[0][t] = g_k[base + t];
    else        qsh[0][t] = g_q[base + t];
    float vcur = g_v[base + t];
    float vold = 0.f;                    // S = 0 initially
    __syncthreads();

    for (int s = 0; s < SEQ; s++) {
        const int cur = s & 1;
        const int nxt = cur ^ 1;
        const bool more = (s + 1) < SEQ;

        // issue prefetch for step s+1 early (latency covered by phase1/2)
        float knv = 0.f, qnv = 0.f, vnv = 0.f;
        if (more) {
            const size_t nb = base + (size_t)(s + 1) * HIDDEN;
            if (g == 0) knv = g_k[nb + t];
            else        qnv = g_q[nb + t];
            vnv = g_v[nb + t];
        }

        // phase1: delta + rank-1 update on own rows, from k_s (shared, f4)
        const float bd = BETA_F * clip1(vcur - vold);
        float lmax = 0.f;
        {
            const float4* kc = (const float4*)&ksh[cur][rb];
#pragma unroll
            for (int c = 0; c < 8; c++) {
                const float4 k4 = kc[c];
                float s0 = Scol[c*4+0] + clip1(bd * k4.x);
                float s1 = Scol[c*4+1] + clip1(bd * k4.y);
                float s2 = Scol[c*4+2] + clip1(bd * k4.z);
                float s3 = Scol[c*4+3] + clip1(bd * k4.w);
                Scol[c*4+0] = s0; Scol[c*4+1] = s1;
                Scol[c*4+2] = s2; Scol[c*4+3] = s3;
                lmax = fmaxf(lmax, fmaxf(fmaxf(fabsf(s0), fabsf(s1)),
                                         fmaxf(fabsf(s2), fabsf(s3))));
            }
        }
        const int over = __syncthreads_or(lmax > STATE_CAP_F);     // barA

        // phase2: rescale + publish column + stage next k/q
        if (over) {
#pragma unroll
            for (int i = 0; i < 32; i++) Scol[i] *= 0.9f;
        }
#pragma unroll
        for (int i = 0; i < 32; i++) Ssh[rb + i][t] = Scol[i];
        if (more) {
            if (g == 0) ksh[nxt][t] = knv;
            else        qsh[nxt][t] = qnv;
        }
        __syncthreads();                                            // barB

        // phase3a: o_s partial = sum_j Ssh[t][rb+j] * q_s[rb+j]
        {
            const float4* qc = (const float4*)&qsh[cur][rb];
            float o0 = 0.f, o1 = 0.f, o2 = 0.f, o3 = 0.f;
#pragma unroll
            for (int c = 0; c < 8; c++) {
                const float4 q4 = qc[c];
                o0 += Ssh[t][rb + c*4 + 0] * q4.x;
                o1 += Ssh[t][rb + c*4 + 1] * q4.y;
                o2 += Ssh[t][rb + c*4 + 2] * q4.z;
                o3 += Ssh[t][rb + c*4 + 3] * q4.w;
            }
            po[g][t] = (o0 + o1) + (o2 + o3);
        }
        // phase3b: vold_{s+1} partial = sum_i k_{s+1}[rb+i] * Scol[i]
        if (more) {
            const float4* kn = (const float4*)&ksh[nxt][rb];
            float p0 = 0.f, p1 = 0.f, p2 = 0.f, p3 = 0.f;
#pragma unroll
            for (int c = 0; c < 8; c++) {
                const float4 k4 = kn[c];
                p0 += k4.x * Scol[c*4+0];
                p1 += k4.y * Scol[c*4+1];
                p2 += k4.z * Scol[c*4+2];
                p3 += k4.w * Scol[c*4+3];
            }
            pd[g][t] = (p0 + p1) + (p2 + p3);
        }
        __syncthreads();                                            // barC

        // phase4: combine + write + roll
        if (g == 0)
            g_o[base + (size_t)s * HIDDEN + t] = clip1(po[0][t] + po[1][t]);
        if (more) {
            vold = pd[0][t] + pd[1][t];
            vcur = vnv;
        }
    }

    // final state: state_out[b][h][d][e]; thread (t,g) writes its 32 rows
    float* sp = state_out + (size_t)bh * HEAD_DIM * HEAD_DIM;
#pragma unroll
    for (int i = 0; i < 32; i++)
        sp[(rb + i) * HEAD_DIM + t] = Scol[i];
}

// ---------------------------------------------------------------------------
extern "C" void kernel_launch(void* const* d_in, const int* in_sizes, int n_in,
                              void* d_out, int out_size)
{
    (void)in_sizes; (void)n_in;
    const float* x  = (const float*)d_in[0];
    const float* Wq = (const float*)d_in[1];
    const float* bq = (const float*)d_in[2];
    const float* Wk = (const float*)d_in[3];
    const float* bk = (const float*)d_in[4];
    const float* Wv = (const float*)d_in[5];
    const float* bv = (const float*)d_in[6];
    const float* Wo = (const float*)d_in[7];
    const float* bo = (const float*)d_in[8];

    float* o_ptr = nullptr;
    cudaGetSymbolAddress((void**)&o_ptr, g_o);

    const int OUT_ELEMS   = ROWS * HIDDEN;                         // 4194304
    const int STATE_ELEMS = BATCH * HEADS * HEAD_DIM * HEAD_DIM;   // 262144

    float* state_out;
    if (out_size >= OUT_ELEMS + STATE_ELEMS) {
        state_out = (float*)d_out + OUT_ELEMS;
    } else {
        cudaGetSymbolAddress((void**)&state_out, g_state_scratch);
    }

    // 1) QKV projections (single launch, z selects tensor)
    dim3 gq(HIDDEN / 128, ROWS / 128, 3);
    gemm_qkv_kernel<<<gq, 256>>>(x, Wq, bq, Wk, bk, Wv, bv);

    // 2) L2 norm of q and k: 131072 head vectors, 1 warp each
    l2norm_kernel<<<(2 * ROWS * HEADS) / 8, 256>>>();

    // 3) sequential delta-rule scan, one 128-thread block per (b,h)
    scan_kernel<<<BATCH * HEADS, 128>>>(state_out);

    // 4) output projection -> d_out
    dim3 go(HIDDEN / 128, ROWS / 128);
    gemm_nt_kernel<<<go, 256>>>(o_ptr, Wo, bo, (float*)d_out,
                                HIDDEN, HIDDEN);
}

// round 7
// speedup vs baseline: 1.3097x; 1.3097x over previous
#include <cuda_runtime.h>
#include <cstdint>

#define HIDDEN    1024
#define HEADS     16
#define HEAD_DIM  64
#define BATCH     4
#define SEQ       1024
#define ROWS      (BATCH*SEQ)        // 4096
#define BETA_F    0.9f
#define CLAMP_F   1.0f
#define STATE_CAP_F 10.0f
#define BK        16

// ---------------- scratch (static device arrays are allowed) ---------------
__device__ float g_q[ROWS*HIDDEN];
__device__ float g_k[ROWS*HIDDEN];
__device__ float g_v[ROWS*HIDDEN];
__device__ float g_o[ROWS*HIDDEN];
__device__ float g_state_scratch[BATCH*HEADS*HEAD_DIM*HEAD_DIM];

// ---------------------------------------------------------------------------
// GEMM: C[m,n] = sum_k A[m,k]*B[n,k] + bias[n]   (A:[M,K], B:[N,K] row-major)
// BM=BN=128, BK=16, 256 threads, 8x8 microtile, double-buffered smem.
// norm (runtime): L2-normalize each output row per 64-wide head before store
// (head = 8 consecutive tx lanes; reduce via shfl_xor 1/2/4). Epilogue-only.
// ---------------------------------------------------------------------------
__device__ __forceinline__ void gemm_nt_body(
    const float* __restrict__ A, const float* __restrict__ B,
    const float* __restrict__ bias, float* __restrict__ C,
    int N, int K, int m0, int n0, bool norm)
{
    __shared__ float As[2][BK][128];   // 16 KB
    __shared__ float Bs[2][BK][128];   // 16 KB

    const int tid  = threadIdx.x;
    const int tx   = tid & 15;
    const int ty   = tid >> 4;
    const int lrow = tid >> 1;
    const int lcol = (tid & 1) * 8;

    const float* Aptr = A + (size_t)(m0 + lrow) * K + lcol;
    const float* Bptr = B + (size_t)(n0 + lrow) * K + lcol;

    float acc[8][8];
#pragma unroll
    for (int i = 0; i < 8; i++)
#pragma unroll
        for (int j = 0; j < 8; j++) acc[i][j] = 0.f;

    float4 a0 = *(const float4*)(Aptr);
    float4 a1 = *(const float4*)(Aptr + 4);
    float4 b0 = *(const float4*)(Bptr);
    float4 b1 = *(const float4*)(Bptr + 4);
    As[0][lcol+0][lrow]=a0.x; As[0][lcol+1][lrow]=a0.y; As[0][lcol+2][lrow]=a0.z; As[0][lcol+3][lrow]=a0.w;
    As[0][lcol+4][lrow]=a1.x; As[0][lcol+5][lrow]=a1.y; As[0][lcol+6][lrow]=a1.z; As[0][lcol+7][lrow]=a1.w;
    Bs[0][lcol+0][lrow]=b0.x; Bs[0][lcol+1][lrow]=b0.y; Bs[0][lcol+2][lrow]=b0.z; Bs[0][lcol+3][lrow]=b0.w;
    Bs[0][lcol+4][lrow]=b1.x; Bs[0][lcol+5][lrow]=b1.y; Bs[0][lcol+6][lrow]=b1.z; Bs[0][lcol+7][lrow]=b1.w;
    __syncthreads();

    int buf = 0;
    for (int k0 = 0; k0 < K; k0 += BK) {
        const bool has_next = (k0 + BK) < K;
        if (has_next) {
            a0 = *(const float4*)(Aptr + k0 + BK);
            a1 = *(const float4*)(Aptr + k0 + BK + 4);
            b0 = *(const float4*)(Bptr + k0 + BK);
            b1 = *(const float4*)(Bptr + k0 + BK + 4);
        }
#pragma unroll
        for (int kk = 0; kk < BK; kk++) {
            float af[8], bf[8];
            *(float4*)(af)     = *(const float4*)&As[buf][kk][ty*8];
            *(float4*)(af + 4) = *(const float4*)&As[buf][kk][ty*8 + 4];
            *(float4*)(bf)     = *(const float4*)&Bs[buf][kk][tx*8];
            *(float4*)(bf + 4) = *(const float4*)&Bs[buf][kk][tx*8 + 4];
#pragma unroll
            for (int i = 0; i < 8; i++)
#pragma unroll
                for (int j = 0; j < 8; j++)
                    acc[i][j] += af[i] * bf[j];
        }
        if (has_next) {
            const int nb = buf ^ 1;
            As[nb][lcol+0][lrow]=a0.x; As[nb][lcol+1][lrow]=a0.y; As[nb][lcol+2][lrow]=a0.z; As[nb][lcol+3][lrow]=a0.w;
            As[nb][lcol+4][lrow]=a1.x; As[nb][lcol+5][lrow]=a1.y; As[nb][lcol+6][lrow]=a1.z; As[nb][lcol+7][lrow]=a1.w;
            Bs[nb][lcol+0][lrow]=b0.x; Bs[nb][lcol+1][lrow]=b0.y; Bs[nb][lcol+2][lrow]=b0.z; Bs[nb][lcol+3][lrow]=b0.w;
            Bs[nb][lcol+4][lrow]=b1.x; Bs[nb][lcol+5][lrow]=b1.y; Bs[nb][lcol+6][lrow]=b1.z; Bs[nb][lcol+7][lrow]=b1.w;
            __syncthreads();
            buf = nb;
        }
    }

    float bv[8];
#pragma unroll
    for (int j = 0; j < 8; j++) bv[j] = bias[n0 + tx*8 + j];

#pragma unroll
    for (int i = 0; i < 8; i++) {
        float c[8];
#pragma unroll
        for (int j = 0; j < 8; j++) c[j] = acc[i][j] + bv[j];
        if (norm) {
            // this thread's 8 cols are 1/8 of a 64-wide head; the 8 lanes
            // sharing the same ty and tx>>3 hold the full head row.
            float ss = 0.f;
#pragma unroll
            for (int j = 0; j < 8; j++) ss += c[j] * c[j];
            ss += __shfl_xor_sync(0xffffffffu, ss, 1);
            ss += __shfl_xor_sync(0xffffffffu, ss, 2);
            ss += __shfl_xor_sync(0xffffffffu, ss, 4);
            float inv = 1.0f / fmaxf(sqrtf(ss), 1e-12f);
#pragma unroll
            for (int j = 0; j < 8; j++) c[j] *= inv;
        }
        float* cp = C + (size_t)(m0 + ty*8 + i) * N + n0 + tx*8;
        float4 c0, c1;
        c0.x=c[0]; c0.y=c[1]; c0.z=c[2]; c0.w=c[3];
        c1.x=c[4]; c1.y=c[5]; c1.z=c[6]; c1.w=c[7];
        *(float4*)(cp)     = c0;
        *(float4*)(cp + 4) = c1;
    }
}

__global__ __launch_bounds__(256) void gemm_nt_kernel(
    const float* __restrict__ A, const float* __restrict__ B,
    const float* __restrict__ bias, float* __restrict__ C,
    int N, int K)
{
    gemm_nt_body(A, B, bias, C, N, K, blockIdx.y * 128, blockIdx.x * 128, false);
}

// One launch computes q, k (normalized) and v (blockIdx.z selects).
__global__ __launch_bounds__(256) void gemm_qkv_kernel(
    const float* __restrict__ X,
    const float* __restrict__ Wq, const float* __restrict__ bq,
    const float* __restrict__ Wk, const float* __restrict__ bk,
    const float* __restrict__ Wv, const float* __restrict__ bv)
{
    const float* W; const float* bias; float* out; bool norm;
    if (blockIdx.z == 0)      { W = Wq; bias = bq; out = g_q; norm = true;  }
    else if (blockIdx.z == 1) { W = Wk; bias = bk; out = g_k; norm = true;  }
    else                      { W = Wv; bias = bv; out = g_v; norm = false; }
    gemm_nt_body(X, W, bias, out, HIDDEN, HIDDEN,
                 blockIdx.y * 128, blockIdx.x * 128, norm);
}

// ---------------------------------------------------------------------------
// Sequential delta-rule scan. One 128-thread block per (b,h).
// Thread (t,g): t=column 0..63, g=row half; owns S[g*32..g*32+31][t] (raw).
// Lazy scale p: true state = p * raw S, folded into the next update / output.
// Inner clip(beta*k*delta) dropped: ||k||2=1 => |k_i|<=1, |delta|<=1, beta=0.9
// => |beta*k_i*delta| <= 0.9 < 1  (clip is identity).
// 3 barriers/step; 2x-unrolled loop so every global load has >= 1 full step
// of latency cover before its consuming barrier.
// ---------------------------------------------------------------------------
__device__ __forceinline__ float clip1(float x) {
    return fminf(fmaxf(x, -CLAMP_F), CLAMP_F);
}

__global__ __launch_bounds__(128) void scan_kernel(float* __restrict__ state_out)
{
    __shared__ float Ssh[HEAD_DIM][68];      // row pitch 68 floats (16B align)
    __shared__ float ksh[2][HEAD_DIM];
    __shared__ float qsh[2][HEAD_DIM];
    __shared__ float pd[2][HEAD_DIM];
    __shared__ float po[2][HEAD_DIM];

    const int tid = threadIdx.x;
    const int t   = tid & 63;
    const int g   = tid >> 6;
    const int rb  = g * 32;
    const int bh  = blockIdx.x;
    const size_t base = (size_t)(bh >> 4) * SEQ * HIDDEN
                      + (size_t)(bh & 15) * HEAD_DIM + t;

    float S[32];
#pragma unroll
    for (int i = 0; i < 32; i++) S[i] = 0.f;

    // prologue: stage step 0; registers hold step-1 k/q and v0,v1
    if (g == 0) ksh[0][t] = g_k[base];
    else        qsh[0][t] = g_q[base];
    float kA = (g == 0) ? g_k[base + HIDDEN] : g_q[base + HIDDEN]; // step s0+1
    float kB = 0.f;                                                // step s0+2
    float vc = g_v[base];              // v at even step
    float vn = g_v[base + HIDDEN];     // v at odd step
    float voldraw = 0.f;               // unscaled k.S from previous step
    float p = 1.f;                     // pending state scale

    __syncthreads();

    for (int s0 = 0; s0 < SEQ; s0 += 2) {
        float kA2 = 0.f, vc2 = 0.f, vn2 = 0.f;

        // ================= even step s0 (buffer 0) =================
        {
            const float bd = BETA_F * clip1(vc - p * voldraw);
            float lmax = 0.f;
            const float4* kc = (const float4*)&ksh[0][rb];
            if (p == 1.f) {
#pragma unroll
                for (int c = 0; c < 8; c++) {
                    const float4 k4 = kc[c];
                    float x0=fmaf(bd,k4.x,S[c*4+0]), x1=fmaf(bd,k4.y,S[c*4+1]);
                    float x2=fmaf(bd,k4.z,S[c*4+2]), x3=fmaf(bd,k4.w,S[c*4+3]);
                    S[c*4+0]=x0; S[c*4+1]=x1; S[c*4+2]=x2; S[c*4+3]=x3;
                    lmax = fmaxf(lmax, fmaxf(fmaxf(fabsf(x0),fabsf(x1)),
                                             fmaxf(fabsf(x2),fabsf(x3))));
                }
            } else {
#pragma unroll
                for (int c = 0; c < 8; c++) {
                    const float4 k4 = kc[c];
                    float x0=fmaf(p,S[c*4+0],bd*k4.x), x1=fmaf(p,S[c*4+1],bd*k4.y);
                    float x2=fmaf(p,S[c*4+2],bd*k4.z), x3=fmaf(p,S[c*4+3],bd*k4.w);
                    S[c*4+0]=x0; S[c*4+1]=x1; S[c*4+2]=x2; S[c*4+3]=x3;
                    lmax = fmaxf(lmax, fmaxf(fmaxf(fabsf(x0),fabsf(x1)),
                                             fmaxf(fabsf(x2),fabsf(x3))));
                }
            }
            const int over = __syncthreads_or(lmax > STATE_CAP_F);   // barA
            const float pn = over ? 0.9f : 1.0f;

            // publish raw S; stage k/q for step s0+1 (loaded a full step ago)
#pragma unroll
            for (int i = 0; i < 32; i++) Ssh[rb + i][t] = S[i];
            if (g == 0) ksh[1][t] = kA; else qsh[1][t] = kA;
            __syncthreads();                                         // barB

            // issue ALL global loads for steps s0+2 / s0+3 now
            if (s0 + 2 < SEQ) {
                const size_t b2 = base + (size_t)(s0 + 2) * HIDDEN;
                kB  = (g == 0) ? g_k[b2] : g_q[b2];
                vc2 = g_v[b2];
                if (s0 + 3 < SEQ) {
                    const size_t b3 = b2 + HIDDEN;
                    kA2 = (g == 0) ? g_k[b3] : g_q[b3];
                    vn2 = g_v[b3];
                }
            }
            // o_s partial: row t of raw S x q_s
            {
                const float4* qc = (const float4*)&qsh[0][rb];
                const float4* sr = (const float4*)&Ssh[t][rb];
                float o0=0.f,o1=0.f,o2=0.f,o3=0.f;
#pragma unroll
                for (int c = 0; c < 8; c++) {
                    const float4 q4 = qc[c]; const float4 s4 = sr[c];
                    o0 += s4.x*q4.x; o1 += s4.y*q4.y;
                    o2 += s4.z*q4.z; o3 += s4.w*q4.w;
                }
                po[g][t] = (o0+o1)+(o2+o3);
            }
            // vold_{s+1} partial: k_{s+1} x raw S (register columns)
            {
                const float4* kn = (const float4*)&ksh[1][rb];
                float d0=0.f,d1=0.f,d2=0.f,d3=0.f;
#pragma unroll
                for (int c = 0; c < 8; c++) {
                    const float4 k4 = kn[c];
                    d0 += k4.x*S[c*4+0]; d1 += k4.y*S[c*4+1];
                    d2 += k4.z*S[c*4+2]; d3 += k4.w*S[c*4+3];
                }
                pd[g][t] = (d0+d1)+(d2+d3);
            }
            __syncthreads();                                         // barC

            if (g == 0)
                g_o[base + (size_t)s0 * HIDDEN] = clip1(pn * (po[0][t] + po[1][t]));
            voldraw = pd[0][t] + pd[1][t];
            p = pn;
        }

        // ================= odd step s0+1 (buffer 1) =================
        {
            const int s = s0 + 1;
            const float bd = BETA_F * clip1(vn - p * voldraw);
            float lmax = 0.f;
            const float4* kc = (const float4*)&ksh[1][rb];
            if (p == 1.f) {
#pragma unroll
                for (int c = 0; c < 8; c++) {
                    const float4 k4 = kc[c];
                    float x0=fmaf(bd,k4.x,S[c*4+0]), x1=fmaf(bd,k4.y,S[c*4+1]);
                    float x2=fmaf(bd,k4.z,S[c*4+2]), x3=fmaf(bd,k4.w,S[c*4+3]);
                    S[c*4+0]=x0; S[c*4+1]=x1; S[c*4+2]=x2; S[c*4+3]=x3;
                    lmax = fmaxf(lmax, fmaxf(fmaxf(fabsf(x0),fabsf(x1)),
                                             fmaxf(fabsf(x2),fabsf(x3))));
                }
            } else {
#pragma unroll
                for (int c = 0; c < 8; c++) {
                    const float4 k4 = kc[c];
                    float x0=fmaf(p,S[c*4+0],bd*k4.x), x1=fmaf(p,S[c*4+1],bd*k4.y);
                    float x2=fmaf(p,S[c*4+2],bd*k4.z), x3=fmaf(p,S[c*4+3],bd*k4.w);
                    S[c*4+0]=x0; S[c*4+1]=x1; S[c*4+2]=x2; S[c*4+3]=x3;
                    lmax = fmaxf(lmax, fmaxf(fmaxf(fabsf(x0),fabsf(x1)),
                                             fmaxf(fabsf(x2),fabsf(x3))));
                }
            }
            const int over = __syncthreads_or(lmax > STATE_CAP_F);   // barA
            const float pn = over ? 0.9f : 1.0f;

#pragma unroll
            for (int i = 0; i < 32; i++) Ssh[rb + i][t] = S[i];
            const bool more = (s + 1) < SEQ;
            if (more) { if (g == 0) ksh[0][t] = kB; else qsh[0][t] = kB; }
            __syncthreads();                                         // barB

            {
                const float4* qc = (const float4*)&qsh[1][rb];
                const float4* sr = (const float4*)&Ssh[t][rb];
                float o0=0.f,o1=0.f,o2=0.f,o3=0.f;
#pragma unroll
                for (int c = 0; c < 8; c++) {
                    const float4 q4 = qc[c]; const float4 s4 = sr[c];
                    o0 += s4.x*q4.x; o1 += s4.y*q4.y;
                    o2 += s4.z*q4.z; o3 += s4.w*q4.w;
                }
                po[g][t] = (o0+o1)+(o2+o3);
            }
            if (more) {
                const float4* kn = (const float4*)&ksh[0][rb];
                float d0=0.f,d1=0.f,d2=0.f,d3=0.f;
#pragma unroll
                for (int c = 0; c < 8; c++) {
                    const float4 k4 = kn[c];
                    d0 += k4.x*S[c*4+0]; d1 += k4.y*S[c*4+1];
                    d2 += k4.z*S[c*4+2]; d3 += k4.w*S[c*4+3];
                }
                pd[g][t] = (d0+d1)+(d2+d3);
            }
            __syncthreads();                                         // barC

            if (g == 0)
                g_o[base + (size_t)s * HIDDEN] = clip1(pn * (po[0][t] + po[1][t]));
            voldraw = pd[0][t] + pd[1][t];
            p = pn;
        }

        kA = kA2; vc = vc2; vn = vn2;
    }

    // final true state = p * raw S
    float* sp = state_out + (size_t)bh * HEAD_DIM * HEAD_DIM;
#pragma unroll
    for (int i = 0; i < 32; i++)
        sp[(rb + i) * HEAD_DIM + t] = p * S[i];
}

// ---------------------------------------------------------------------------
extern "C" void kernel_launch(void* const* d_in, const int* in_sizes, int n_in,
                              void* d_out, int out_size)
{
    (void)in_sizes; (void)n_in;
    const float* x  = (const float*)d_in[0];
    const float* Wq = (const float*)d_in[1];
    const float* bq = (const float*)d_in[2];
    const float* Wk = (const float*)d_in[3];
    const float* bk = (const float*)d_in[4];
    const float* Wv = (const float*)d_in[5];
    const float* bv = (const float*)d_in[6];
    const float* Wo = (const float*)d_in[7];
    const float* bo = (const float*)d_in[8];

    float* o_ptr = nullptr;
    cudaGetSymbolAddress((void**)&o_ptr, g_o);

    const int OUT_ELEMS   = ROWS * HIDDEN;
    const int STATE_ELEMS = BATCH * HEADS * HEAD_DIM * HEAD_DIM;

    float* state_out;
    if (out_size >= OUT_ELEMS + STATE_ELEMS) {
        state_out = (float*)d_out + OUT_ELEMS;
    } else {
        cudaGetSymbolAddress((void**)&state_out, g_state_scratch);
    }

    // 1) QKV projections with fused q/k L2-normalization
    dim3 gq(HIDDEN / 128, ROWS / 128, 3);
    gemm_qkv_kernel<<<gq, 256>>>(x, Wq, bq, Wk, bk, Wv, bv);

    // 2) sequential delta-rule scan, one 128-thread block per (b,h)
    scan_kernel<<<BATCH * HEADS, 128>>>(state_out);

    // 3) output projection -> d_out
    dim3 go(HIDDEN / 128, ROWS / 128);
    gemm_nt_kernel<<<go, 256>>>(o_ptr, Wo, bo, (float*)d_out,
                                HIDDEN, HIDDEN);
}

// round 8
// speedup vs baseline: 1.3152x; 1.0042x over previous
#include <cuda_runtime.h>
#include <cstdint>

#define HIDDEN    1024
#define HEADS     16
#define HEAD_DIM  64
#define BATCH     4
#define SEQ       1024
#define ROWS      (BATCH*SEQ)        // 4096
#define BETA_F    0.9f
#define CLAMP_F   1.0f
#define STATE_CAP_F 10.0f
#define BK        16

// ---------------- scratch (static device arrays are allowed) ---------------
__device__ float g_q[ROWS*HIDDEN];
__device__ float g_k[ROWS*HIDDEN];
__device__ float g_v[ROWS*HIDDEN];
__device__ float g_o[ROWS*HIDDEN];
__device__ float g_state_scratch[BATCH*HEADS*HEAD_DIM*HEAD_DIM];

// ---------------------------------------------------------------------------
// GEMM: C[m,n] = sum_k A[m,k]*B[n,k] + bias[n]   (A:[M,K], B:[N,K] row-major)
// BM=BN=128, BK=16, 256 threads, 8x8 microtile, double-buffered smem.
// norm (runtime): L2-normalize each output row per 64-wide head before store.
// ---------------------------------------------------------------------------
__device__ __forceinline__ void gemm_nt_body(
    const float* __restrict__ A, const float* __restrict__ B,
    const float* __restrict__ bias, float* __restrict__ C,
    int N, int K, int m0, int n0, bool norm)
{
    __shared__ float As[2][BK][128];   // 16 KB
    __shared__ float Bs[2][BK][128];   // 16 KB

    const int tid  = threadIdx.x;
    const int tx   = tid & 15;
    const int ty   = tid >> 4;
    const int lrow = tid >> 1;
    const int lcol = (tid & 1) * 8;

    const float* Aptr = A + (size_t)(m0 + lrow) * K + lcol;
    const float* Bptr = B + (size_t)(n0 + lrow) * K + lcol;

    float acc[8][8];
#pragma unroll
    for (int i = 0; i < 8; i++)
#pragma unroll
        for (int j = 0; j < 8; j++) acc[i][j] = 0.f;

    float4 a0 = *(const float4*)(Aptr);
    float4 a1 = *(const float4*)(Aptr + 4);
    float4 b0 = *(const float4*)(Bptr);
    float4 b1 = *(const float4*)(Bptr + 4);
    As[0][lcol+0][lrow]=a0.x; As[0][lcol+1][lrow]=a0.y; As[0][lcol+2][lrow]=a0.z; As[0][lcol+3][lrow]=a0.w;
    As[0][lcol+4][lrow]=a1.x; As[0][lcol+5][lrow]=a1.y; As[0][lcol+6][lrow]=a1.z; As[0][lcol+7][lrow]=a1.w;
    Bs[0][lcol+0][lrow]=b0.x; Bs[0][lcol+1][lrow]=b0.y; Bs[0][lcol+2][lrow]=b0.z; Bs[0][lcol+3][lrow]=b0.w;
    Bs[0][lcol+4][lrow]=b1.x; Bs[0][lcol+5][lrow]=b1.y; Bs[0][lcol+6][lrow]=b1.z; Bs[0][lcol+7][lrow]=b1.w;
    __syncthreads();

    int buf = 0;
    for (int k0 = 0; k0 < K; k0 += BK) {
        const bool has_next = (k0 + BK) < K;
        if (has_next) {
            a0 = *(const float4*)(Aptr + k0 + BK);
            a1 = *(const float4*)(Aptr + k0 + BK + 4);
            b0 = *(const float4*)(Bptr + k0 + BK);
            b1 = *(const float4*)(Bptr + k0 + BK + 4);
        }
#pragma unroll
        for (int kk = 0; kk < BK; kk++) {
            float af[8], bf[8];
            *(float4*)(af)     = *(const float4*)&As[buf][kk][ty*8];
            *(float4*)(af + 4) = *(const float4*)&As[buf][kk][ty*8 + 4];
            *(float4*)(bf)     = *(const float4*)&Bs[buf][kk][tx*8];
            *(float4*)(bf + 4) = *(const float4*)&Bs[buf][kk][tx*8 + 4];
#pragma unroll
            for (int i = 0; i < 8; i++)
#pragma unroll
                for (int j = 0; j < 8; j++)
                    acc[i][j] += af[i] * bf[j];
        }
        if (has_next) {
            const int nb = buf ^ 1;
            As[nb][lcol+0][lrow]=a0.x; As[nb][lcol+1][lrow]=a0.y; As[nb][lcol+2][lrow]=a0.z; As[nb][lcol+3][lrow]=a0.w;
            As[nb][lcol+4][lrow]=a1.x; As[nb][lcol+5][lrow]=a1.y; As[nb][lcol+6][lrow]=a1.z; As[nb][lcol+7][lrow]=a1.w;
            Bs[nb][lcol+0][lrow]=b0.x; Bs[nb][lcol+1][lrow]=b0.y; Bs[nb][lcol+2][lrow]=b0.z; Bs[nb][lcol+3][lrow]=b0.w;
            Bs[nb][lcol+4][lrow]=b1.x; Bs[nb][lcol+5][lrow]=b1.y; Bs[nb][lcol+6][lrow]=b1.z; Bs[nb][lcol+7][lrow]=b1.w;
            __syncthreads();
            buf = nb;
        }
    }

    float bv[8];
#pragma unroll
    for (int j = 0; j < 8; j++) bv[j] = bias[n0 + tx*8 + j];

#pragma unroll
    for (int i = 0; i < 8; i++) {
        float c[8];
#pragma unroll
        for (int j = 0; j < 8; j++) c[j] = acc[i][j] + bv[j];
        if (norm) {
            float ss = 0.f;
#pragma unroll
            for (int j = 0; j < 8; j++) ss += c[j] * c[j];
            ss += __shfl_xor_sync(0xffffffffu, ss, 1);
            ss += __shfl_xor_sync(0xffffffffu, ss, 2);
            ss += __shfl_xor_sync(0xffffffffu, ss, 4);
            float inv = 1.0f / fmaxf(sqrtf(ss), 1e-12f);
#pragma unroll
            for (int j = 0; j < 8; j++) c[j] *= inv;
        }
        float* cp = C + (size_t)(m0 + ty*8 + i) * N + n0 + tx*8;
        float4 c0, c1;
        c0.x=c[0]; c0.y=c[1]; c0.z=c[2]; c0.w=c[3];
        c1.x=c[4]; c1.y=c[5]; c1.z=c[6]; c1.w=c[7];
        *(float4*)(cp)     = c0;
        *(float4*)(cp + 4) = c1;
    }
}

__global__ __launch_bounds__(256) void gemm_nt_kernel(
    const float* __restrict__ A, const float* __restrict__ B,
    const float* __restrict__ bias, float* __restrict__ C,
    int N, int K)
{
    gemm_nt_body(A, B, bias, C, N, K, blockIdx.y * 128, blockIdx.x * 128, false);
}

__global__ __launch_bounds__(256) void gemm_qkv_kernel(
    const float* __restrict__ X,
    const float* __restrict__ Wq, const float* __restrict__ bq,
    const float* __restrict__ Wk, const float* __restrict__ bk,
    const float* __restrict__ Wv, const float* __restrict__ bv)
{
    const float* W; const float* bias; float* out; bool norm;
    if (blockIdx.z == 0)      { W = Wq; bias = bq; out = g_q; norm = true;  }
    else if (blockIdx.z == 1) { W = Wk; bias = bk; out = g_k; norm = true;  }
    else                      { W = Wv; bias = bv; out = g_v; norm = false; }
    gemm_nt_body(X, W, bias, out, HIDDEN, HIDDEN,
                 blockIdx.y * 128, blockIdx.x * 128, norm);
}

// ---------------------------------------------------------------------------
// Sequential delta-rule scan, 2 barriers/step.
// One 128-thread block per (b,h). Thread (t,g): t=column, g=row half.
// Owns raw S[g*32..g*32+31][t]; true state = p * raw S (lazy 0.9 fold).
// Schedule per step s:
//   top   : issue global prefetch for step s+2 (full step of cover)
//   pre-A : fused update  S = p*S + bd*k_s   (reads ksh[cur]), lmax,
//           publish Ssh (only o needs it), stage ksh/qsh[nxt] = step s+1
//   barA  : __syncthreads_or(lmax > cap)  -> pn
//   post-A: po = row(Ssh) . q_s    AND    pd = k_{s+1} . S (registers)
//   barB  : plain
//   tail  : o_s = clip(pn*(po0+po1)) -> gmem ; voldraw = pd0+pd1 ; roll
// Shared hazards all have >= 2 barriers between conflicting accesses.
// Inner clip(beta*k*delta) dropped (provably identity: ||k||=1,|delta|<=1).
// ---------------------------------------------------------------------------
__device__ __forceinline__ float clip1(float x) {
    return fminf(fmaxf(x, -CLAMP_F), CLAMP_F);
}

__global__ __launch_bounds__(128) void scan_kernel(float* __restrict__ state_out)
{
    __shared__ float Ssh[HEAD_DIM][68];      // row pitch 68 floats (16B align)
    __shared__ float ksh[2][HEAD_DIM];
    __shared__ float qsh[2][HEAD_DIM];
    __shared__ float pd[2][HEAD_DIM];
    __shared__ float po[2][HEAD_DIM];

    const int tid = threadIdx.x;
    const int t   = tid & 63;
    const int g   = tid >> 6;
    const int rb  = g * 32;
    const int bh  = blockIdx.x;
    const size_t base = (size_t)(bh >> 4) * SEQ * HIDDEN
                      + (size_t)(bh & 15) * HEAD_DIM + t;

    float S[32];
#pragma unroll
    for (int i = 0; i < 32; i++) S[i] = 0.f;

    // prologue: stage step 0 into buffer 0; register pipeline for s+1, s+2
    if (g == 0) ksh[0][t] = g_k[base];
    else        qsh[0][t] = g_q[base];
    float kA = (g == 0) ? g_k[base + HIDDEN] : g_q[base + HIDDEN]; // step 1
    float kB = 0.f;                                                // step 2
    float vC = g_v[base];              // v_s
    float vA = g_v[base + HIDDEN];     // v_{s+1}
    float vB = 0.f;                    // v_{s+2}
    float voldraw = 0.f;               // k_s . raw S_{s-1}
    float p = 1.f;                     // pending state scale
    __syncthreads();

    for (int s = 0; s < SEQ; s++) {
        const int cur = s & 1;
        const int nxt = cur ^ 1;

        // prefetch step s+2 (consumed at stage in step s+1 -> full step cover)
        if (s + 2 < SEQ) {
            const size_t b2 = base + (size_t)(s + 2) * HIDDEN;
            kB = (g == 0) ? g_k[b2] : g_q[b2];
            vB = g_v[b2];
        }

        // fused update: S = p*S + bd*k_s ; track max|.|
        const float bd = BETA_F * clip1(vC - p * voldraw);
        float lmax = 0.f;
        {
            const float4* kc = (const float4*)&ksh[cur][rb];
            if (p == 1.f) {
#pragma unroll
                for (int c = 0; c < 8; c++) {
                    const float4 k4 = kc[c];
                    float x0=fmaf(bd,k4.x,S[c*4+0]), x1=fmaf(bd,k4.y,S[c*4+1]);
                    float x2=fmaf(bd,k4.z,S[c*4+2]), x3=fmaf(bd,k4.w,S[c*4+3]);
                    S[c*4+0]=x0; S[c*4+1]=x1; S[c*4+2]=x2; S[c*4+3]=x3;
                    lmax = fmaxf(lmax, fmaxf(fmaxf(fabsf(x0),fabsf(x1)),
                                             fmaxf(fabsf(x2),fabsf(x3))));
                }
            } else {
#pragma unroll
                for (int c = 0; c < 8; c++) {
                    const float4 k4 = kc[c];
                    float x0=fmaf(p,S[c*4+0],bd*k4.x), x1=fmaf(p,S[c*4+1],bd*k4.y);
                    float x2=fmaf(p,S[c*4+2],bd*k4.z), x3=fmaf(p,S[c*4+3],bd*k4.w);
                    S[c*4+0]=x0; S[c*4+1]=x1; S[c*4+2]=x2; S[c*4+3]=x3;
                    lmax = fmaxf(lmax, fmaxf(fmaxf(fabsf(x0),fabsf(x1)),
                                             fmaxf(fabsf(x2),fabsf(x3))));
                }
            }
        }
        // publish raw S (o-path only) and stage k/q for step s+1
#pragma unroll
        for (int i = 0; i < 32; i++) Ssh[rb + i][t] = S[i];
        if (s + 1 < SEQ) {
            if (g == 0) ksh[nxt][t] = kA; else qsh[nxt][t] = kA;
        }

        const int over = __syncthreads_or(lmax > STATE_CAP_F);       // barA
        const float pn = over ? 0.9f : 1.0f;

        // o_s partial: row t of raw S x q_s
        {
            const float4* qc = (const float4*)&qsh[cur][rb];
            const float4* sr = (const float4*)&Ssh[t][rb];
            float o0=0.f,o1=0.f,o2=0.f,o3=0.f;
#pragma unroll
            for (int c = 0; c < 8; c++) {
                const float4 q4 = qc[c]; const float4 s4 = sr[c];
                o0 += s4.x*q4.x; o1 += s4.y*q4.y;
                o2 += s4.z*q4.z; o3 += s4.w*q4.w;
            }
            po[g][t] = (o0+o1)+(o2+o3);
        }
        // vold_{s+1} partial: k_{s+1} x raw S (register columns)
        if (s + 1 < SEQ) {
            const float4* kn = (const float4*)&ksh[nxt][rb];
            float d0=0.f,d1=0.f,d2=0.f,d3=0.f;
#pragma unroll
            for (int c = 0; c < 8; c++) {
                const float4 k4 = kn[c];
                d0 += k4.x*S[c*4+0]; d1 += k4.y*S[c*4+1];
                d2 += k4.z*S[c*4+2]; d3 += k4.w*S[c*4+3];
            }
            pd[g][t] = (d0+d1)+(d2+d3);
        }
        __syncthreads();                                             // barB

        if (g == 0)
            g_o[base + (size_t)s * HIDDEN] = clip1(pn * (po[0][t] + po[1][t]));
        voldraw = pd[0][t] + pd[1][t];
        p  = pn;
        vC = vA; vA = vB; kA = kB;
    }

    // final true state = p * raw S : state_out[b][h][d][e]
    float* sp = state_out + (size_t)bh * HEAD_DIM * HEAD_DIM;
#pragma unroll
    for (int i = 0; i < 32; i++)
        sp[(rb + i) * HEAD_DIM + t] = p * S[i];
}

// ---------------------------------------------------------------------------
extern "C" void kernel_launch(void* const* d_in, const int* in_sizes, int n_in,
                              void* d_out, int out_size)
{
    (void)in_sizes; (void)n_in;
    const float* x  = (const float*)d_in[0];
    const float* Wq = (const float*)d_in[1];
    const float* bq = (const float*)d_in[2];
    const float* Wk = (const float*)d_in[3];
    const float* bk = (const float*)d_in[4];
    const float* Wv = (const float*)d_in[5];
    const float* bv = (const float*)d_in[6];
    const float* Wo = (const float*)d_in[7];
    const float* bo = (const float*)d_in[8];

    float* o_ptr = nullptr;
    cudaGetSymbolAddress((void**)&o_ptr, g_o);

    const int OUT_ELEMS   = ROWS * HIDDEN;
    const int STATE_ELEMS = BATCH * HEADS * HEAD_DIM * HEAD_DIM;

    float* state_out;
    if (out_size >= OUT_ELEMS + STATE_ELEMS) {
        state_out = (float*)d_out + OUT_ELEMS;
    } else {
        cudaGetSymbolAddress((void**)&state_out, g_state_scratch);
    }

    // 1) QKV projections with fused q/k L2-normalization
    dim3 gq(HIDDEN / 128, ROWS / 128, 3);
    gemm_qkv_kernel<<<gq, 256>>>(x, Wq, bq, Wk, bk, Wv, bv);

    // 2) sequential delta-rule scan, one 128-thread block per (b,h)
    scan_kernel<<<BATCH * HEADS, 128>>>(state_out);

    // 3) output projection -> d_out
    dim3 go(HIDDEN / 128, ROWS / 128);
    gemm_nt_kernel<<<go, 256>>>(o_ptr, Wo, bo, (float*)d_out,
                                HIDDEN, HIDDEN);
}

// round 9
// speedup vs baseline: 1.6864x; 1.2823x over previous
#include <cuda_runtime.h>
#include <cuda_bf16.h>
#include <cstdint>

#define HIDDEN    1024
#define HEADS     16
#define HEAD_DIM  64
#define BATCH     4
#define SEQ       1024
#define ROWS      (BATCH*SEQ)        // 4096
#define BETA_F    0.9f
#define CLAMP_F   1.0f
#define STATE_CAP_F 10.0f
#define PITCH     40                 // ushorts per smem row (80 B)

// ---------------- scratch (static device arrays are allowed) ---------------
__device__ float g_q[ROWS*HIDDEN];
__device__ float g_k[ROWS*HIDDEN];
__device__ float g_v[ROWS*HIDDEN];
__device__ float g_o[ROWS*HIDDEN];
__device__ float g_state_scratch[BATCH*HEADS*HEAD_DIM*HEAD_DIM];

// ---------------------------------------------------------------------------
// bf16x3 tensor-core GEMM: C[m,n] = sum_k A[m,k]*B[n,k] + bias[n]
// A:[M,K] row-major, B:[N,K] row-major (NT). BM=BN=128, BK=32, 256 thr.
// Each fp32 x is split hi+lo (bf16); acc += hi*hi + hi*lo + lo*hi (fp32).
// Warp grid 4(M) x 2(N): warp tile 32x64 -> a 64-wide head is warp-local,
// so the optional q/k L2-norm is a quad shfl in the epilogue.
// ---------------------------------------------------------------------------
#define MMA16816(d, a, b0, b1)                                              \
    asm volatile("mma.sync.aligned.m16n8k16.row.col.f32.bf16.bf16.f32 "     \
                 "{%0,%1,%2,%3}, {%4,%5,%6,%7}, {%8,%9}, {%0,%1,%2,%3};"    \
                 : "+f"((d)[0]), "+f"((d)[1]), "+f"((d)[2]), "+f"((d)[3])   \
                 : "r"((a)[0]), "r"((a)[1]), "r"((a)[2]), "r"((a)[3]),      \
                   "r"(b0), "r"(b1))

#define LDSM4(r, addr)                                                      \
    asm volatile("ldmatrix.sync.aligned.m8n8.x4.shared.b16 "                \
                 "{%0,%1,%2,%3}, [%4];"                                     \
                 : "=r"((r)[0]), "=r"((r)[1]), "=r"((r)[2]), "=r"((r)[3])   \
                 : "r"(addr))

__device__ __forceinline__ void bf16_split2(float x0, float x1,
                                            uint32_t& hi, uint32_t& lo)
{
    __nv_bfloat16 h0 = __float2bfloat16_rn(x0);
    __nv_bfloat16 h1 = __float2bfloat16_rn(x1);
    __nv_bfloat16 l0 = __float2bfloat16_rn(x0 - __bfloat162float(h0));
    __nv_bfloat16 l1 = __float2bfloat16_rn(x1 - __bfloat162float(h1));
    hi = (uint32_t)__bfloat16_as_ushort(h0) |
         ((uint32_t)__bfloat16_as_ushort(h1) << 16);
    lo = (uint32_t)__bfloat16_as_ushort(l0) |
         ((uint32_t)__bfloat16_as_ushort(l1) << 16);
}

__device__ __forceinline__ void gemm_bf16_body(
    const float* __restrict__ A, const float* __restrict__ B,
    const float* __restrict__ bias, float* __restrict__ C,
    int N, int K, int m0, int n0, bool norm)
{
    __shared__ unsigned short sA_hi[128*PITCH];  // 10 KB each
    __shared__ unsigned short sA_lo[128*PITCH];
    __shared__ unsigned short sB_hi[128*PITCH];
    __shared__ unsigned short sB_lo[128*PITCH];

    const int tid  = threadIdx.x;
    const int lane = tid & 31;
    const int warp = tid >> 5;
    const int wm   = warp & 3;       // 0..3  -> m offset wm*32
    const int wn   = warp >> 2;      // 0..1  -> n offset wn*64

    // conversion-load assignment: thread -> (row, 16-col half)
    const int arow = tid >> 1;           // 0..127
    const int acol = (tid & 1) * 16;     // 0 or 16
    const float* Ap = A + (size_t)(m0 + arow) * K + acol;
    const float* Bp = B + (size_t)(n0 + arow) * K + acol;
    const int s32   = arow * (PITCH/2) + acol/2;   // u32 index into smem rows

    uint32_t* sA_hi32 = (uint32_t*)sA_hi;  uint32_t* sA_lo32 = (uint32_t*)sA_lo;
    uint32_t* sB_hi32 = (uint32_t*)sB_hi;  uint32_t* sB_lo32 = (uint32_t*)sB_lo;

    const uint32_t baseA_hi = (uint32_t)__cvta_generic_to_shared(sA_hi);
    const uint32_t baseA_lo = (uint32_t)__cvta_generic_to_shared(sA_lo);
    const uint32_t baseB_hi = (uint32_t)__cvta_generic_to_shared(sB_hi);
    const uint32_t baseB_lo = (uint32_t)__cvta_generic_to_shared(sB_lo);

    // ldmatrix per-lane offsets
    const int a_row_l = lane & 15;                      // within 16-row tile
    const int a_col_l = (lane >> 4) << 3;               // 0 or 8
    const int b_n_l   = ((lane >> 4) << 3) + (lane & 7);// within 16-n pair
    const int b_k_l   = ((lane >> 3) & 1) << 3;         // 0 or 8

    float acc[2][8][4];
#pragma unroll
    for (int mi = 0; mi < 2; mi++)
#pragma unroll
        for (int nj = 0; nj < 8; nj++)
#pragma unroll
            for (int r = 0; r < 4; r++) acc[mi][nj][r] = 0.f;

    // prefetch tile 0
    float4 a4[4], b4[4];
#pragma unroll
    for (int i = 0; i < 4; i++) {
        a4[i] = *(const float4*)(Ap + 4*i);
        b4[i] = *(const float4*)(Bp + 4*i);
    }

    for (int k0 = 0; k0 < K; k0 += 32) {
        __syncthreads();   // previous iteration's ldmatrix reads are done
        // convert + store this tile
#pragma unroll
        for (int i = 0; i < 4; i++) {
            uint32_t h, l;
            bf16_split2(a4[i].x, a4[i].y, h, l);
            sA_hi32[s32 + 2*i]     = h; sA_lo32[s32 + 2*i]     = l;
            bf16_split2(a4[i].z, a4[i].w, h, l);
            sA_hi32[s32 + 2*i + 1] = h; sA_lo32[s32 + 2*i + 1] = l;
            bf16_split2(b4[i].x, b4[i].y, h, l);
            sB_hi32[s32 + 2*i]     = h; sB_lo32[s32 + 2*i]     = l;
            bf16_split2(b4[i].z, b4[i].w, h, l);
            sB_hi32[s32 + 2*i + 1] = h; sB_lo32[s32 + 2*i + 1] = l;
        }
        __syncthreads();

        // prefetch next tile while doing the mma block
        if (k0 + 32 < K) {
#pragma unroll
            for (int i = 0; i < 4; i++) {
                a4[i] = *(const float4*)(Ap + k0 + 32 + 4*i);
                b4[i] = *(const float4*)(Bp + k0 + 32 + 4*i);
            }
        }

#pragma unroll
        for (int ks = 0; ks < 2; ks++) {
            const int koff = ks * 16;
            // A frags: mi in {0,1}, rows wm*32+mi*16+(lane&15), col koff+a_col_l
            uint32_t afh[2][4], afl[2][4];
#pragma unroll
            for (int mi = 0; mi < 2; mi++) {
                const uint32_t off =
                    ((uint32_t)((wm*32 + mi*16 + a_row_l) * PITCH
                                + koff + a_col_l)) * 2u;
                LDSM4(afh[mi], baseA_hi + off);
                LDSM4(afl[mi], baseA_lo + off);
            }
            // B frags: jp in 0..3 covers n-tile pair (2jp, 2jp+1)
            uint32_t bfh[4][4], bfl[4][4];
#pragma unroll
            for (int jp = 0; jp < 4; jp++) {
                const uint32_t off =
                    ((uint32_t)((wn*64 + jp*16 + b_n_l) * PITCH
                                + koff + b_k_l)) * 2u;
                LDSM4(bfh[jp], baseB_hi + off);
                LDSM4(bfl[jp], baseB_lo + off);
            }
#pragma unroll
            for (int mi = 0; mi < 2; mi++) {
#pragma unroll
                for (int jp = 0; jp < 4; jp++) {
                    // n-tile 2jp uses (b[0], b[1]); 2jp+1 uses (b[2], b[3])
                    MMA16816(acc[mi][2*jp],   afh[mi], bfh[jp][0], bfh[jp][1]);
                    MMA16816(acc[mi][2*jp],   afh[mi], bfl[jp][0], bfl[jp][1]);
                    MMA16816(acc[mi][2*jp],   afl[mi], bfh[jp][0], bfh[jp][1]);
                    MMA16816(acc[mi][2*jp+1], afh[mi], bfh[jp][2], bfh[jp][3]);
                    MMA16816(acc[mi][2*jp+1], afh[mi], bfl[jp][2], bfl[jp][3]);
                    MMA16816(acc[mi][2*jp+1], afl[mi], bfh[jp][2], bfh[jp][3]);
                }
            }
        }
    }

    // ---------------- epilogue: bias (+ optional per-head L2 norm) ---------
    const int qr = lane >> 2;          // 0..7  row within 16-row tile
    const int qc = (lane & 3) * 2;     // 0,2,4,6 col within 8-col tile

#pragma unroll
    for (int mi = 0; mi < 2; mi++) {
        float c[8][4];
#pragma unroll
        for (int nj = 0; nj < 8; nj++) {
            const float b0 = bias[n0 + wn*64 + nj*8 + qc];
            const float b1 = bias[n0 + wn*64 + nj*8 + qc + 1];
            c[nj][0] = acc[mi][nj][0] + b0;
            c[nj][1] = acc[mi][nj][1] + b1;
            c[nj][2] = acc[mi][nj][2] + b0;
            c[nj][3] = acc[mi][nj][3] + b1;
        }
        if (norm) {
            // head (64 cols) = whole warp-n tile; quad lanes share each row
            float ss0 = 0.f, ss1 = 0.f;
#pragma unroll
            for (int nj = 0; nj < 8; nj++) {
                ss0 += c[nj][0]*c[nj][0] + c[nj][1]*c[nj][1];
                ss1 += c[nj][2]*c[nj][2] + c[nj][3]*c[nj][3];
            }
            ss0 += __shfl_xor_sync(0xffffffffu, ss0, 1);
            ss0 += __shfl_xor_sync(0xffffffffu, ss0, 2);
            ss1 += __shfl_xor_sync(0xffffffffu, ss1, 1);
            ss1 += __shfl_xor_sync(0xffffffffu, ss1, 2);
            const float inv0 = 1.0f / fmaxf(sqrtf(ss0), 1e-12f);
            const float inv1 = 1.0f / fmaxf(sqrtf(ss1), 1e-12f);
#pragma unroll
            for (int nj = 0; nj < 8; nj++) {
                c[nj][0] *= inv0; c[nj][1] *= inv0;
                c[nj][2] *= inv1; c[nj][3] *= inv1;
            }
        }
        const int row_lo = m0 + wm*32 + mi*16 + qr;
#pragma unroll
        for (int nj = 0; nj < 8; nj++) {
            const int col = n0 + wn*64 + nj*8 + qc;
            float2 lo; lo.x = c[nj][0]; lo.y = c[nj][1];
            float2 hi; hi.x = c[nj][2]; hi.y = c[nj][3];
            *(float2*)(C + (size_t)row_lo       * N + col) = lo;
            *(float2*)(C + (size_t)(row_lo + 8) * N + col) = hi;
        }
    }
}

__global__ __launch_bounds__(256) void gemm_bf16_nt_kernel(
    const float* __restrict__ A, const float* __restrict__ B,
    const float* __restrict__ bias, float* __restrict__ C,
    int N, int K)
{
    gemm_bf16_body(A, B, bias, C, N, K,
                   blockIdx.y * 128, blockIdx.x * 128, false);
}

__global__ __launch_bounds__(256) void gemm_bf16_qkv_kernel(
    const float* __restrict__ X,
    const float* __restrict__ Wq, const float* __restrict__ bq,
    const float* __restrict__ Wk, const float* __restrict__ bk,
    const float* __restrict__ Wv, const float* __restrict__ bv)
{
    const float* W; const float* bias; float* out; bool norm;
    if (blockIdx.z == 0)      { W = Wq; bias = bq; out = g_q; norm = true;  }
    else if (blockIdx.z == 1) { W = Wk; bias = bk; out = g_k; norm = true;  }
    else                      { W = Wv; bias = bv; out = g_v; norm = false; }
    gemm_bf16_body(X, W, bias, out, HIDDEN, HIDDEN,
                   blockIdx.y * 128, blockIdx.x * 128, norm);
}

// ---------------------------------------------------------------------------
// Sequential delta-rule scan (unchanged from R8): 2 barriers/step.
// ---------------------------------------------------------------------------
__device__ __forceinline__ float clip1(float x) {
    return fminf(fmaxf(x, -CLAMP_F), CLAMP_F);
}

__global__ __launch_bounds__(128) void scan_kernel(float* __restrict__ state_out)
{
    __shared__ float Ssh[HEAD_DIM][68];
    __shared__ float ksh[2][HEAD_DIM];
    __shared__ float qsh[2][HEAD_DIM];
    __shared__ float pd[2][HEAD_DIM];
    __shared__ float po[2][HEAD_DIM];

    const int tid = threadIdx.x;
    const int t   = tid & 63;
    const int g   = tid >> 6;
    const int rb  = g * 32;
    const int bh  = blockIdx.x;
    const size_t base = (size_t)(bh >> 4) * SEQ * HIDDEN
                      + (size_t)(bh & 15) * HEAD_DIM + t;

    float S[32];
#pragma unroll
    for (int i = 0; i < 32; i++) S[i] = 0.f;

    if (g == 0) ksh[0][t] = g_k[base];
    else        qsh[0][t] = g_q[base];
    float kA = (g == 0) ? g_k[base + HIDDEN] : g_q[base + HIDDEN];
    float kB = 0.f;
    float vC = g_v[base];
    float vA = g_v[base + HIDDEN];
    float vB = 0.f;
    float voldraw = 0.f;
    float p = 1.f;
    __syncthreads();

    for (int s = 0; s < SEQ; s++) {
        const int cur = s & 1;
        const int nxt = cur ^ 1;

        if (s + 2 < SEQ) {
            const size_t b2 = base + (size_t)(s + 2) * HIDDEN;
            kB = (g == 0) ? g_k[b2] : g_q[b2];
            vB = g_v[b2];
        }

        const float bd = BETA_F * clip1(vC - p * voldraw);
        float lmax = 0.f;
        {
            const float4* kc = (const float4*)&ksh[cur][rb];
            if (p == 1.f) {
#pragma unroll
                for (int c = 0; c < 8; c++) {
                    const float4 k4 = kc[c];
                    float x0=fmaf(bd,k4.x,S[c*4+0]), x1=fmaf(bd,k4.y,S[c*4+1]);
                    float x2=fmaf(bd,k4.z,S[c*4+2]), x3=fmaf(bd,k4.w,S[c*4+3]);
                    S[c*4+0]=x0; S[c*4+1]=x1; S[c*4+2]=x2; S[c*4+3]=x3;
                    lmax = fmaxf(lmax, fmaxf(fmaxf(fabsf(x0),fabsf(x1)),
                                             fmaxf(fabsf(x2),fabsf(x3))));
                }
            } else {
#pragma unroll
                for (int c = 0; c < 8; c++) {
                    const float4 k4 = kc[c];
                    float x0=fmaf(p,S[c*4+0],bd*k4.x), x1=fmaf(p,S[c*4+1],bd*k4.y);
                    float x2=fmaf(p,S[c*4+2],bd*k4.z), x3=fmaf(p,S[c*4+3],bd*k4.w);
                    S[c*4+0]=x0; S[c*4+1]=x1; S[c*4+2]=x2; S[c*4+3]=x3;
                    lmax = fmaxf(lmax, fmaxf(fmaxf(fabsf(x0),fabsf(x1)),
                                             fmaxf(fabsf(x2),fabsf(x3))));
                }
            }
        }
#pragma unroll
        for (int i = 0; i < 32; i++) Ssh[rb + i][t] = S[i];
        if (s + 1 < SEQ) {
            if (g == 0) ksh[nxt][t] = kA; else qsh[nxt][t] = kA;
        }

        const int over = __syncthreads_or(lmax > STATE_CAP_F);       // barA
        const float pn = over ? 0.9f : 1.0f;

        {
            const float4* qc = (const float4*)&qsh[cur][rb];
            const float4* sr = (const float4*)&Ssh[t][rb];
            float o0=0.f,o1=0.f,o2=0.f,o3=0.f;
#pragma unroll
            for (int c = 0; c < 8; c++) {
                const float4 q4 = qc[c]; const float4 s4 = sr[c];
                o0 += s4.x*q4.x; o1 += s4.y*q4.y;
                o2 += s4.z*q4.z; o3 += s4.w*q4.w;
            }
            po[g][t] = (o0+o1)+(o2+o3);
        }
        if (s + 1 < SEQ) {
            const float4* kn = (const float4*)&ksh[nxt][rb];
            float d0=0.f,d1=0.f,d2=0.f,d3=0.f;
#pragma unroll
            for (int c = 0; c < 8; c++) {
                const float4 k4 = kn[c];
                d0 += k4.x*S[c*4+0]; d1 += k4.y*S[c*4+1];
                d2 += k4.z*S[c*4+2]; d3 += k4.w*S[c*4+3];
            }
            pd[g][t] = (d0+d1)+(d2+d3);
        }
        __syncthreads();                                             // barB

        if (g == 0)
            g_o[base + (size_t)s * HIDDEN] = clip1(pn * (po[0][t] + po[1][t]));
        voldraw = pd[0][t] + pd[1][t];
        p  = pn;
        vC = vA; vA = vB; kA = kB;
    }

    float* sp = state_out + (size_t)bh * HEAD_DIM * HEAD_DIM;
#pragma unroll
    for (int i = 0; i < 32; i++)
        sp[(rb + i) * HEAD_DIM + t] = p * S[i];
}

// ---------------------------------------------------------------------------
extern "C" void kernel_launch(void* const* d_in, const int* in_sizes, int n_in,
                              void* d_out, int out_size)
{
    (void)in_sizes; (void)n_in;
    const float* x  = (const float*)d_in[0];
    const float* Wq = (const float*)d_in[1];
    const float* bq = (const float*)d_in[2];
    const float* Wk = (const float*)d_in[3];
    const float* bk = (const float*)d_in[4];
    const float* Wv = (const float*)d_in[5];
    const float* bv = (const float*)d_in[6];
    const float* Wo = (const float*)d_in[7];
    const float* bo = (const float*)d_in[8];

    float* o_ptr = nullptr;
    cudaGetSymbolAddress((void**)&o_ptr, g_o);

    const int OUT_ELEMS   = ROWS * HIDDEN;
    const int STATE_ELEMS = BATCH * HEADS * HEAD_DIM * HEAD_DIM;

    float* state_out;
    if (out_size >= OUT_ELEMS + STATE_ELEMS) {
        state_out = (float*)d_out + OUT_ELEMS;
    } else {
        cudaGetSymbolAddress((void**)&state_out, g_state_scratch);
    }

    // 1) QKV projections (tensor-core bf16x3) with fused q/k L2-norm
    dim3 gq(HIDDEN / 128, ROWS / 128, 3);
    gemm_bf16_qkv_kernel<<<gq, 256>>>(x, Wq, bq, Wk, bk, Wv, bv);

    // 2) sequential delta-rule scan
    scan_kernel<<<BATCH * HEADS, 128>>>(state_out);

    // 3) output projection (tensor-core bf16x3) -> d_out
    dim3 go(HIDDEN / 128, ROWS / 128);
    gemm_bf16_nt_kernel<<<go, 256>>>(o_ptr, Wo, bo, (float*)d_out,
                                     HIDDEN, HIDDEN);
}

// round 10
// speedup vs baseline: 1.7899x; 1.0613x over previous
#include <cuda_runtime.h>
#include <cuda_bf16.h>
#include <cstdint>

#define HIDDEN    1024
#define HEADS     16
#define HEAD_DIM  64
#define BATCH     4
#define SEQ       1024
#define ROWS      (BATCH*SEQ)        // 4096
#define BETA_F    0.9f
#define CLAMP_F   1.0f
#define STATE_CAP_F 10.0f
#define PITCH     40                 // ushorts per smem row (80 B, bank-clean)

// dynamic smem: 2 stages x 4 arrays x 128 rows x PITCH ushorts
#define STAGE_SHORTS (4*128*PITCH)   // 20480
#define STAGE_BYTES  (STAGE_SHORTS*2)        // 40960
#define ARR_BYTES    (128*PITCH*2)           // 10240
#define SMEM_TOTAL_B (2*STAGE_BYTES)         // 81920

// ---------------- scratch (static device arrays are allowed) ---------------
__device__ float g_q[ROWS*HIDDEN];
__device__ float g_k[ROWS*HIDDEN];
__device__ float g_v[ROWS*HIDDEN];
__device__ float g_o[ROWS*HIDDEN];
__device__ float g_state_scratch[BATCH*HEADS*HEAD_DIM*HEAD_DIM];

// ---------------------------------------------------------------------------
// bf16x3 tensor-core GEMM, double-buffered: one __syncthreads per K-tile.
// C[m,n] = sum_k A[m,k]*B[n,k] + bias[n];  BM=BN=128, BK=32, 256 threads.
// x = hi + lo (bf16 pair); acc += hi*hi + hi*lo + lo*hi  (fp32 accum).
// Warp grid 4(M) x 2(N); warp tile 32x64 (one head per warp-n for the norm).
// ---------------------------------------------------------------------------
#define MMA16816(d, a, b0, b1)                                              \
    asm volatile("mma.sync.aligned.m16n8k16.row.col.f32.bf16.bf16.f32 "     \
                 "{%0,%1,%2,%3}, {%4,%5,%6,%7}, {%8,%9}, {%0,%1,%2,%3};"    \
                 : "+f"((d)[0]), "+f"((d)[1]), "+f"((d)[2]), "+f"((d)[3])   \
                 : "r"((a)[0]), "r"((a)[1]), "r"((a)[2]), "r"((a)[3]),      \
                   "r"(b0), "r"(b1))

#define LDSM4(r, addr)                                                      \
    asm volatile("ldmatrix.sync.aligned.m8n8.x4.shared.b16 "                \
                 "{%0,%1,%2,%3}, [%4];"                                     \
                 : "=r"((r)[0]), "=r"((r)[1]), "=r"((r)[2]), "=r"((r)[3])   \
                 : "r"(addr))

__device__ __forceinline__ void bf16_split2(float x0, float x1,
                                            uint32_t& hi, uint32_t& lo)
{
    __nv_bfloat16 h0 = __float2bfloat16_rn(x0);
    __nv_bfloat16 h1 = __float2bfloat16_rn(x1);
    __nv_bfloat16 l0 = __float2bfloat16_rn(x0 - __bfloat162float(h0));
    __nv_bfloat16 l1 = __float2bfloat16_rn(x1 - __bfloat162float(h1));
    hi = (uint32_t)__bfloat16_as_ushort(h0) |
         ((uint32_t)__bfloat16_as_ushort(h1) << 16);
    lo = (uint32_t)__bfloat16_as_ushort(l0) |
         ((uint32_t)__bfloat16_as_ushort(l1) << 16);
}

__device__ __forceinline__ void gemm_bf16_body(
    const float* __restrict__ A, const float* __restrict__ B,
    const float* __restrict__ bias, float* __restrict__ C,
    int N, int K, int m0, int n0, bool norm)
{
    extern __shared__ unsigned short dynsm[];

    const int tid  = threadIdx.x;
    const int lane = tid & 31;
    const int warp = tid >> 5;
    const int wm   = warp & 3;       // m offset wm*32
    const int wn   = warp >> 2;      // n offset wn*64

    // conversion-load assignment: thread -> (row, 16-col half)
    const int arow = tid >> 1;           // 0..127
    const int acol = (tid & 1) * 16;     // 0 or 16
    const float* Ap = A + (size_t)(m0 + arow) * K + acol;
    const float* Bp = B + (size_t)(n0 + arow) * K + acol;
    const int s32   = arow * (PITCH/2) + acol/2;   // u32 index within array

    const uint32_t smbase = (uint32_t)__cvta_generic_to_shared(dynsm);

    // ldmatrix per-lane offsets
    const int a_row_l = lane & 15;
    const int a_col_l = (lane >> 4) << 3;
    const int b_n_l   = ((lane >> 4) << 3) + (lane & 7);
    const int b_k_l   = ((lane >> 3) & 1) << 3;

    float acc[2][8][4];
#pragma unroll
    for (int mi = 0; mi < 2; mi++)
#pragma unroll
        for (int nj = 0; nj < 8; nj++)
#pragma unroll
            for (int r = 0; r < 4; r++) acc[mi][nj][r] = 0.f;

    // prologue: load + convert + store tile 0 into stage 0
    float4 a4[4], b4[4];
#pragma unroll
    for (int i = 0; i < 4; i++) {
        a4[i] = *(const float4*)(Ap + 4*i);
        b4[i] = *(const float4*)(Bp + 4*i);
    }
    {
        uint32_t* Ah = (uint32_t*)((char*)dynsm + 0*ARR_BYTES);
        uint32_t* Al = (uint32_t*)((char*)dynsm + 1*ARR_BYTES);
        uint32_t* Bh = (uint32_t*)((char*)dynsm + 2*ARR_BYTES);
        uint32_t* Bl = (uint32_t*)((char*)dynsm + 3*ARR_BYTES);
#pragma unroll
        for (int i = 0; i < 4; i++) {
            uint32_t h, l;
            bf16_split2(a4[i].x, a4[i].y, h, l);
            Ah[s32 + 2*i]     = h; Al[s32 + 2*i]     = l;
            bf16_split2(a4[i].z, a4[i].w, h, l);
            Ah[s32 + 2*i + 1] = h; Al[s32 + 2*i + 1] = l;
            bf16_split2(b4[i].x, b4[i].y, h, l);
            Bh[s32 + 2*i]     = h; Bl[s32 + 2*i]     = l;
            bf16_split2(b4[i].z, b4[i].w, h, l);
            Bh[s32 + 2*i + 1] = h; Bl[s32 + 2*i + 1] = l;
        }
    }
    __syncthreads();

    for (int k0 = 0; k0 < K; k0 += 32) {
        const int cur = (k0 >> 5) & 1;
        const int nxt = cur ^ 1;
        const bool has_next = (k0 + 32) < K;

        // issue global loads for the next tile first (max latency cover)
        if (has_next) {
#pragma unroll
            for (int i = 0; i < 4; i++) {
                a4[i] = *(const float4*)(Ap + k0 + 32 + 4*i);
                b4[i] = *(const float4*)(Bp + k0 + 32 + 4*i);
            }
        }

        // mma block on current stage
        const uint32_t stA_hi = smbase + cur*STAGE_BYTES + 0*ARR_BYTES;
        const uint32_t stA_lo = smbase + cur*STAGE_BYTES + 1*ARR_BYTES;
        const uint32_t stB_hi = smbase + cur*STAGE_BYTES + 2*ARR_BYTES;
        const uint32_t stB_lo = smbase + cur*STAGE_BYTES + 3*ARR_BYTES;

#pragma unroll
        for (int ks = 0; ks < 2; ks++) {
            const int koff = ks * 16;
            uint32_t afh[2][4], afl[2][4];
#pragma unroll
            for (int mi = 0; mi < 2; mi++) {
                const uint32_t off =
                    ((uint32_t)((wm*32 + mi*16 + a_row_l) * PITCH
                                + koff + a_col_l)) * 2u;
                LDSM4(afh[mi], stA_hi + off);
                LDSM4(afl[mi], stA_lo + off);
            }
            uint32_t bfh[4][4], bfl[4][4];
#pragma unroll
            for (int jp = 0; jp < 4; jp++) {
                const uint32_t off =
                    ((uint32_t)((wn*64 + jp*16 + b_n_l) * PITCH
                                + koff + b_k_l)) * 2u;
                LDSM4(bfh[jp], stB_hi + off);
                LDSM4(bfl[jp], stB_lo + off);
            }
#pragma unroll
            for (int mi = 0; mi < 2; mi++) {
#pragma unroll
                for (int jp = 0; jp < 4; jp++) {
                    MMA16816(acc[mi][2*jp],   afh[mi], bfh[jp][0], bfh[jp][1]);
                    MMA16816(acc[mi][2*jp],   afh[mi], bfl[jp][0], bfl[jp][1]);
                    MMA16816(acc[mi][2*jp],   afl[mi], bfh[jp][0], bfh[jp][1]);
                    MMA16816(acc[mi][2*jp+1], afh[mi], bfh[jp][2], bfh[jp][3]);
                    MMA16816(acc[mi][2*jp+1], afh[mi], bfl[jp][2], bfl[jp][3]);
                    MMA16816(acc[mi][2*jp+1], afl[mi], bfh[jp][2], bfh[jp][3]);
                }
            }
        }

        // convert + store the next tile into the other stage (overlaps mma drain)
        if (has_next) {
            uint32_t* Ah = (uint32_t*)((char*)dynsm + nxt*STAGE_BYTES + 0*ARR_BYTES);
            uint32_t* Al = (uint32_t*)((char*)dynsm + nxt*STAGE_BYTES + 1*ARR_BYTES);
            uint32_t* Bh = (uint32_t*)((char*)dynsm + nxt*STAGE_BYTES + 2*ARR_BYTES);
            uint32_t* Bl = (uint32_t*)((char*)dynsm + nxt*STAGE_BYTES + 3*ARR_BYTES);
#pragma unroll
            for (int i = 0; i < 4; i++) {
                uint32_t h, l;
                bf16_split2(a4[i].x, a4[i].y, h, l);
                Ah[s32 + 2*i]     = h; Al[s32 + 2*i]     = l;
                bf16_split2(a4[i].z, a4[i].w, h, l);
                Ah[s32 + 2*i + 1] = h; Al[s32 + 2*i + 1] = l;
                bf16_split2(b4[i].x, b4[i].y, h, l);
                Bh[s32 + 2*i]     = h; Bl[s32 + 2*i]     = l;
                bf16_split2(b4[i].z, b4[i].w, h, l);
                Bh[s32 + 2*i + 1] = h; Bl[s32 + 2*i + 1] = l;
            }
        }
        __syncthreads();   // one barrier per K-tile
    }

    // ---------------- epilogue: bias (+ optional per-head L2 norm) ---------
    const int qr = lane >> 2;
    const int qc = (lane & 3) * 2;

#pragma unroll
    for (int mi = 0; mi < 2; mi++) {
        float c[8][4];
#pragma unroll
        for (int nj = 0; nj < 8; nj++) {
            const float b0 = bias[n0 + wn*64 + nj*8 + qc];
            const float b1 = bias[n0 + wn*64 + nj*8 + qc + 1];
            c[nj][0] = acc[mi][nj][0] + b0;
            c[nj][1] = acc[mi][nj][1] + b1;
            c[nj][2] = acc[mi][nj][2] + b0;
            c[nj][3] = acc[mi][nj][3] + b1;
        }
        if (norm) {
            float ss0 = 0.f, ss1 = 0.f;
#pragma unroll
            for (int nj = 0; nj < 8; nj++) {
                ss0 += c[nj][0]*c[nj][0] + c[nj][1]*c[nj][1];
                ss1 += c[nj][2]*c[nj][2] + c[nj][3]*c[nj][3];
            }
            ss0 += __shfl_xor_sync(0xffffffffu, ss0, 1);
            ss0 += __shfl_xor_sync(0xffffffffu, ss0, 2);
            ss1 += __shfl_xor_sync(0xffffffffu, ss1, 1);
            ss1 += __shfl_xor_sync(0xffffffffu, ss1, 2);
            const float inv0 = 1.0f / fmaxf(sqrtf(ss0), 1e-12f);
            const float inv1 = 1.0f / fmaxf(sqrtf(ss1), 1e-12f);
#pragma unroll
            for (int nj = 0; nj < 8; nj++) {
                c[nj][0] *= inv0; c[nj][1] *= inv0;
                c[nj][2] *= inv1; c[nj][3] *= inv1;
            }
        }
        const int row_lo = m0 + wm*32 + mi*16 + qr;
#pragma unroll
        for (int nj = 0; nj < 8; nj++) {
            const int col = n0 + wn*64 + nj*8 + qc;
            float2 lo; lo.x = c[nj][0]; lo.y = c[nj][1];
            float2 hi; hi.x = c[nj][2]; hi.y = c[nj][3];
            *(float2*)(C + (size_t)row_lo       * N + col) = lo;
            *(float2*)(C + (size_t)(row_lo + 8) * N + col) = hi;
        }
    }
}

__global__ __launch_bounds__(256) void gemm_bf16_nt_kernel(
    const float* __restrict__ A, const float* __restrict__ B,
    const float* __restrict__ bias, float* __restrict__ C,
    int N, int K)
{
    gemm_bf16_body(A, B, bias, C, N, K,
                   blockIdx.y * 128, blockIdx.x * 128, false);
}

__global__ __launch_bounds__(256) void gemm_bf16_qkv_kernel(
    const float* __restrict__ X,
    const float* __restrict__ Wq, const float* __restrict__ bq,
    const float* __restrict__ Wk, const float* __restrict__ bk,
    const float* __restrict__ Wv, const float* __restrict__ bv)
{
    const float* W; const float* bias; float* out; bool norm;
    if (blockIdx.z == 0)      { W = Wq; bias = bq; out = g_q; norm = true;  }
    else if (blockIdx.z == 1) { W = Wk; bias = bk; out = g_k; norm = true;  }
    else                      { W = Wv; bias = bv; out = g_v; norm = false; }
    gemm_bf16_body(X, W, bias, out, HIDDEN, HIDDEN,
                   blockIdx.y * 128, blockIdx.x * 128, norm);
}

// ---------------------------------------------------------------------------
// Sequential delta-rule scan (unchanged from R8): 2 barriers/step.
// ---------------------------------------------------------------------------
__device__ __forceinline__ float clip1(float x) {
    return fminf(fmaxf(x, -CLAMP_F), CLAMP_F);
}

__global__ __launch_bounds__(128) void scan_kernel(float* __restrict__ state_out)
{
    __shared__ float Ssh[HEAD_DIM][68];
    __shared__ float ksh[2][HEAD_DIM];
    __shared__ float qsh[2][HEAD_DIM];
    __shared__ float pd[2][HEAD_DIM];
    __shared__ float po[2][HEAD_DIM];

    const int tid = threadIdx.x;
    const int t   = tid & 63;
    const int g   = tid >> 6;
    const int rb  = g * 32;
    const int bh  = blockIdx.x;
    const size_t base = (size_t)(bh >> 4) * SEQ * HIDDEN
                      + (size_t)(bh & 15) * HEAD_DIM + t;

    float S[32];
#pragma unroll
    for (int i = 0; i < 32; i++) S[i] = 0.f;

    if (g == 0) ksh[0][t] = g_k[base];
    else        qsh[0][t] = g_q[base];
    float kA = (g == 0) ? g_k[base + HIDDEN] : g_q[base + HIDDEN];
    float kB = 0.f;
    float vC = g_v[base];
    float vA = g_v[base + HIDDEN];
    float vB = 0.f;
    float voldraw = 0.f;
    float p = 1.f;
    __syncthreads();

    for (int s = 0; s < SEQ; s++) {
        const int cur = s & 1;
        const int nxt = cur ^ 1;

        if (s + 2 < SEQ) {
            const size_t b2 = base + (size_t)(s + 2) * HIDDEN;
            kB = (g == 0) ? g_k[b2] : g_q[b2];
            vB = g_v[b2];
        }

        const float bd = BETA_F * clip1(vC - p * voldraw);
        float lmax = 0.f;
        {
            const float4* kc = (const float4*)&ksh[cur][rb];
            if (p == 1.f) {
#pragma unroll
                for (int c = 0; c < 8; c++) {
                    const float4 k4 = kc[c];
                    float x0=fmaf(bd,k4.x,S[c*4+0]), x1=fmaf(bd,k4.y,S[c*4+1]);
                    float x2=fmaf(bd,k4.z,S[c*4+2]), x3=fmaf(bd,k4.w,S[c*4+3]);
                    S[c*4+0]=x0; S[c*4+1]=x1; S[c*4+2]=x2; S[c*4+3]=x3;
                    lmax = fmaxf(lmax, fmaxf(fmaxf(fabsf(x0),fabsf(x1)),
                                             fmaxf(fabsf(x2),fabsf(x3))));
                }
            } else {
#pragma unroll
                for (int c = 0; c < 8; c++) {
                    const float4 k4 = kc[c];
                    float x0=fmaf(p,S[c*4+0],bd*k4.x), x1=fmaf(p,S[c*4+1],bd*k4.y);
                    float x2=fmaf(p,S[c*4+2],bd*k4.z), x3=fmaf(p,S[c*4+3],bd*k4.w);
                    S[c*4+0]=x0; S[c*4+1]=x1; S[c*4+2]=x2; S[c*4+3]=x3;
                    lmax = fmaxf(lmax, fmaxf(fmaxf(fabsf(x0),fabsf(x1)),
                                             fmaxf(fabsf(x2),fabsf(x3))));
                }
            }
        }
#pragma unroll
        for (int i = 0; i < 32; i++) Ssh[rb + i][t] = S[i];
        if (s + 1 < SEQ) {
            if (g == 0) ksh[nxt][t] = kA; else qsh[nxt][t] = kA;
        }

        const int over = __syncthreads_or(lmax > STATE_CAP_F);       // barA
        const float pn = over ? 0.9f : 1.0f;

        {
            const float4* qc = (const float4*)&qsh[cur][rb];
            const float4* sr = (const float4*)&Ssh[t][rb];
            float o0=0.f,o1=0.f,o2=0.f,o3=0.f;
#pragma unroll
            for (int c = 0; c < 8; c++) {
                const float4 q4 = qc[c]; const float4 s4 = sr[c];
                o0 += s4.x*q4.x; o1 += s4.y*q4.y;
                o2 += s4.z*q4.z; o3 += s4.w*q4.w;
            }
            po[g][t] = (o0+o1)+(o2+o3);
        }
        if (s + 1 < SEQ) {
            const float4* kn = (const float4*)&ksh[nxt][rb];
            float d0=0.f,d1=0.f,d2=0.f,d3=0.f;
#pragma unroll
            for (int c = 0; c < 8; c++) {
                const float4 k4 = kn[c];
                d0 += k4.x*S[c*4+0]; d1 += k4.y*S[c*4+1];
                d2 += k4.z*S[c*4+2]; d3 += k4.w*S[c*4+3];
            }
            pd[g][t] = (d0+d1)+(d2+d3);
        }
        __syncthreads();                                             // barB

        if (g == 0)
            g_o[base + (size_t)s * HIDDEN] = clip1(pn * (po[0][t] + po[1][t]));
        voldraw = pd[0][t] + pd[1][t];
        p  = pn;
        vC = vA; vA = vB; kA = kB;
    }

    float* sp = state_out + (size_t)bh * HEAD_DIM * HEAD_DIM;
#pragma unroll
    for (int i = 0; i < 32; i++)
        sp[(rb + i) * HEAD_DIM + t] = p * S[i];
}

// ---------------------------------------------------------------------------
extern "C" void kernel_launch(void* const* d_in, const int* in_sizes, int n_in,
                              void* d_out, int out_size)
{
    (void)in_sizes; (void)n_in;
    const float* x  = (const float*)d_in[0];
    const float* Wq = (const float*)d_in[1];
    const float* bq = (const float*)d_in[2];
    const float* Wk = (const float*)d_in[3];
    const float* bk = (const float*)d_in[4];
    const float* Wv = (const float*)d_in[5];
    const float* bv = (const float*)d_in[6];
    const float* Wo = (const float*)d_in[7];
    const float* bo = (const float*)d_in[8];

    float* o_ptr = nullptr;
    cudaGetSymbolAddress((void**)&o_ptr, g_o);

    const int OUT_ELEMS   = ROWS * HIDDEN;
    const int STATE_ELEMS = BATCH * HEADS * HEAD_DIM * HEAD_DIM;

    float* state_out;
    if (out_size >= OUT_ELEMS + STATE_ELEMS) {
        state_out = (float*)d_out + OUT_ELEMS;
    } else {
        cudaGetSymbolAddress((void**)&state_out, g_state_scratch);
    }

    // opt-in to 80 KB dynamic smem (persistent attribute; idempotent)
    static bool attr_done = false;
    if (!attr_done) {
        cudaFuncSetAttribute(gemm_bf16_qkv_kernel,
                             cudaFuncAttributeMaxDynamicSharedMemorySize,
                             SMEM_TOTAL_B);
        cudaFuncSetAttribute(gemm_bf16_nt_kernel,
                             cudaFuncAttributeMaxDynamicSharedMemorySize,
                             SMEM_TOTAL_B);
        attr_done = true;
    }

    // 1) QKV projections (tensor-core bf16x3, double-buffered) + fused norm
    dim3 gq(HIDDEN / 128, ROWS / 128, 3);
    gemm_bf16_qkv_kernel<<<gq, 256, SMEM_TOTAL_B>>>(x, Wq, bq, Wk, bk, Wv, bv);

    // 2) sequential delta-rule scan
    scan_kernel<<<BATCH * HEADS, 128>>>(state_out);

    // 3) output projection -> d_out
    dim3 go(HIDDEN / 128, ROWS / 128);
    gemm_bf16_nt_kernel<<<go, 256, SMEM_TOTAL_B>>>(o_ptr, Wo, bo, (float*)d_out,
                                                   HIDDEN, HIDDEN);
}

// round 11
// speedup vs baseline: 1.9716x; 1.1015x over previous
#include <cuda_runtime.h>
#include <cuda_bf16.h>
#include <cstdint>

#define HIDDEN    1024
#define HEADS     16
#define HEAD_DIM  64
#define BATCH     4
#define SEQ       1024
#define ROWS      (BATCH*SEQ)        // 4096
#define BETA_F    0.9f
#define CLAMP_F   1.0f
#define STATE_CAP_F 10.0f
#define PITCH     40                 // ushorts per smem row (80 B, bank-clean)

#define ARR_BYTES    (128*PITCH*2)   // 10240
#define STAGE_BYTES  (4*ARR_BYTES)   // 40960
#define SMEM_TOTAL_B (2*STAGE_BYTES) // 81920

// ---------------- scratch (static device arrays are allowed) ---------------
__device__ float g_q[ROWS*HIDDEN];
__device__ float g_k[ROWS*HIDDEN];
__device__ float g_v[ROWS*HIDDEN];
__device__ float g_state_scratch[BATCH*HEADS*HEAD_DIM*HEAD_DIM];

// pre-split bf16 operands
__device__ __nv_bfloat16 g_Xhi[ROWS*HIDDEN],  g_Xlo[ROWS*HIDDEN];
__device__ __nv_bfloat16 g_Whi[4*HIDDEN*HIDDEN], g_Wlo[4*HIDDEN*HIDDEN]; // q,k,v,o
__device__ __nv_bfloat16 g_Ohi[ROWS*HIDDEN],  g_Olo[ROWS*HIDDEN];

// ---------------------------------------------------------------------------
#define MMA16816(d, a, b0, b1)                                              \
    asm volatile("mma.sync.aligned.m16n8k16.row.col.f32.bf16.bf16.f32 "     \
                 "{%0,%1,%2,%3}, {%4,%5,%6,%7}, {%8,%9}, {%0,%1,%2,%3};"    \
                 : "+f"((d)[0]), "+f"((d)[1]), "+f"((d)[2]), "+f"((d)[3])   \
                 : "r"((a)[0]), "r"((a)[1]), "r"((a)[2]), "r"((a)[3]),      \
                   "r"(b0), "r"(b1))

#define LDSM4(r, addr)                                                      \
    asm volatile("ldmatrix.sync.aligned.m8n8.x4.shared.b16 "                \
                 "{%0,%1,%2,%3}, [%4];"                                     \
                 : "=r"((r)[0]), "=r"((r)[1]), "=r"((r)[2]), "=r"((r)[3])   \
                 : "r"(addr))

#define CP16(dst, src)                                                      \
    asm volatile("cp.async.cg.shared.global [%0], [%1], 16;"                \
                 :: "r"(dst), "l"(src))
#define CP_COMMIT() asm volatile("cp.async.commit_group;")
#define CP_WAIT(n)  asm volatile("cp.async.wait_group %0;" :: "n"(n))

__device__ __forceinline__ void bf16_split1(float x, __nv_bfloat16& h,
                                            __nv_bfloat16& l)
{
    h = __float2bfloat16_rn(x);
    l = __float2bfloat16_rn(x - __bfloat162float(h));
}

// ---------------------------------------------------------------------------
// split fp32 -> bf16 hi/lo. z=0: X (ROWS*HIDDEN); z=1..4: Wq,Wk,Wv,Wo.
// 8 elements per thread.
// ---------------------------------------------------------------------------
__global__ __launch_bounds__(256) void split_kernel(
    const float* __restrict__ X,  const float* __restrict__ Wq,
    const float* __restrict__ Wk, const float* __restrict__ Wv,
    const float* __restrict__ Wo)
{
    const int z = blockIdx.z;
    const float* src; __nv_bfloat16* hi; __nv_bfloat16* lo; int n8;
    if (z == 0) { src = X;  hi = g_Xhi; lo = g_Xlo; n8 = ROWS*HIDDEN/8; }
    else {
        const float* ws[4] = {Wq, Wk, Wv, Wo};
        src = ws[z-1];
        hi = g_Whi + (size_t)(z-1)*HIDDEN*HIDDEN;
        lo = g_Wlo + (size_t)(z-1)*HIDDEN*HIDDEN;
        n8 = HIDDEN*HIDDEN/8;
    }
    const int i = blockIdx.x * 256 + threadIdx.x;
    if (i >= n8) return;
    const float4* p = (const float4*)src + 2*(size_t)i;
    float4 x0 = p[0], x1 = p[1];
    __nv_bfloat16 h[8], l[8];
    bf16_split1(x0.x, h[0], l[0]); bf16_split1(x0.y, h[1], l[1]);
    bf16_split1(x0.z, h[2], l[2]); bf16_split1(x0.w, h[3], l[3]);
    bf16_split1(x1.x, h[4], l[4]); bf16_split1(x1.y, h[5], l[5]);
    bf16_split1(x1.z, h[6], l[6]); bf16_split1(x1.w, h[7], l[7]);
    *(uint4*)(hi + 8*(size_t)i) = *(uint4*)h;
    *(uint4*)(lo + 8*(size_t)i) = *(uint4*)l;
}

// ---------------------------------------------------------------------------
// bf16x3 tensor-core GEMM, pre-split operands, cp.async double buffer,
// 2 CTAs/SM. C[m,n] = sum_k A[m,k]*B[n,k] + bias[n]; BM=BN=128, BK=32.
// acc += Ahi*Bhi + Ahi*Blo + Alo*Bhi (fp32). Warp grid 4(M) x 2(N).
// ---------------------------------------------------------------------------
__device__ __forceinline__ void gemm_bf16_body(
    const __nv_bfloat16* __restrict__ Ahi, const __nv_bfloat16* __restrict__ Alo,
    const __nv_bfloat16* __restrict__ Bhi, const __nv_bfloat16* __restrict__ Blo,
    const float* __restrict__ bias, float* __restrict__ C,
    int m0, int n0, bool norm)
{
    extern __shared__ unsigned short dynsm[];
    const int N = HIDDEN, K = HIDDEN;

    const int tid  = threadIdx.x;
    const int lane = tid & 31;
    const int warp = tid >> 5;
    const int wm   = warp & 3;
    const int wn   = warp >> 2;

    // cp.async assignment: thread -> (row, 16-col half) of each array
    const int arow = tid >> 1;
    const int acol = (tid & 1) * 16;
    const size_t aoff0 = (size_t)(m0 + arow) * K + acol;
    const size_t boff0 = (size_t)(n0 + arow) * K + acol;
    const uint32_t smbase = (uint32_t)__cvta_generic_to_shared(dynsm);
    const uint32_t dst0   = smbase + (uint32_t)(arow * (PITCH*2) + (tid & 1) * 32);

    // ldmatrix per-lane offsets
    const int a_row_l = lane & 15;
    const int a_col_l = (lane >> 4) << 3;
    const int b_n_l   = ((lane >> 4) << 3) + (lane & 7);
    const int b_k_l   = ((lane >> 3) & 1) << 3;

    float acc[2][8][4];
#pragma unroll
    for (int mi = 0; mi < 2; mi++)
#pragma unroll
        for (int nj = 0; nj < 8; nj++)
#pragma unroll
            for (int r = 0; r < 4; r++) acc[mi][nj][r] = 0.f;

    // prologue: issue tile 0 into stage 0
    {
        const uint32_t d = dst0;
        CP16(d + 0*ARR_BYTES,      Ahi + aoff0);
        CP16(d + 0*ARR_BYTES + 16, Ahi + aoff0 + 8);
        CP16(d + 1*ARR_BYTES,      Alo + aoff0);
        CP16(d + 1*ARR_BYTES + 16, Alo + aoff0 + 8);
        CP16(d + 2*ARR_BYTES,      Bhi + boff0);
        CP16(d + 2*ARR_BYTES + 16, Bhi + boff0 + 8);
        CP16(d + 3*ARR_BYTES,      Blo + boff0);
        CP16(d + 3*ARR_BYTES + 16, Blo + boff0 + 8);
        CP_COMMIT();
    }

    const int NT = K / 32;   // 32 tiles
    for (int it = 0; it < NT; it++) {
        const int cur = it & 1;
        const int nxt = cur ^ 1;
        const bool hn = (it + 1) < NT;

        if (hn) {
            const int k1 = (it + 1) * 32;
            const uint32_t d = dst0 + nxt * STAGE_BYTES;
            const size_t ao = aoff0 + k1;
            const size_t bo = boff0 + k1;
            CP16(d + 0*ARR_BYTES,      Ahi + ao);
            CP16(d + 0*ARR_BYTES + 16, Ahi + ao + 8);
            CP16(d + 1*ARR_BYTES,      Alo + ao);
            CP16(d + 1*ARR_BYTES + 16, Alo + ao + 8);
            CP16(d + 2*ARR_BYTES,      Bhi + bo);
            CP16(d + 2*ARR_BYTES + 16, Bhi + bo + 8);
            CP16(d + 3*ARR_BYTES,      Blo + bo);
            CP16(d + 3*ARR_BYTES + 16, Blo + bo + 8);
            CP_COMMIT();
            CP_WAIT(1);
        } else {
            CP_WAIT(0);
        }
        __syncthreads();    // cur stage visible to all warps

        const uint32_t stA_hi = smbase + cur*STAGE_BYTES + 0*ARR_BYTES;
        const uint32_t stA_lo = smbase + cur*STAGE_BYTES + 1*ARR_BYTES;
        const uint32_t stB_hi = smbase + cur*STAGE_BYTES + 2*ARR_BYTES;
        const uint32_t stB_lo = smbase + cur*STAGE_BYTES + 3*ARR_BYTES;

#pragma unroll
        for (int ks = 0; ks < 2; ks++) {
            const int koff = ks * 16;
            uint32_t afh[2][4], afl[2][4];
#pragma unroll
            for (int mi = 0; mi < 2; mi++) {
                const uint32_t off =
                    ((uint32_t)((wm*32 + mi*16 + a_row_l) * PITCH
                                + koff + a_col_l)) * 2u;
                LDSM4(afh[mi], stA_hi + off);
                LDSM4(afl[mi], stA_lo + off);
            }
#pragma unroll
            for (int jp = 0; jp < 4; jp++) {
                uint32_t bfh[4], bfl[4];
                const uint32_t off =
                    ((uint32_t)((wn*64 + jp*16 + b_n_l) * PITCH
                                + koff + b_k_l)) * 2u;
                LDSM4(bfh, stB_hi + off);
                LDSM4(bfl, stB_lo + off);
#pragma unroll
                for (int mi = 0; mi < 2; mi++) {
                    MMA16816(acc[mi][2*jp],   afh[mi], bfh[0], bfh[1]);
                    MMA16816(acc[mi][2*jp],   afh[mi], bfl[0], bfl[1]);
                    MMA16816(acc[mi][2*jp],   afl[mi], bfh[0], bfh[1]);
                    MMA16816(acc[mi][2*jp+1], afh[mi], bfh[2], bfh[3]);
                    MMA16816(acc[mi][2*jp+1], afh[mi], bfl[2], bfl[3]);
                    MMA16816(acc[mi][2*jp+1], afl[mi], bfh[2], bfh[3]);
                }
            }
        }
        __syncthreads();    // all warps done with cur before it is re-filled
    }

    // ---------------- epilogue: bias (+ optional per-head L2 norm) ---------
    const int qr = lane >> 2;
    const int qc = (lane & 3) * 2;

#pragma unroll
    for (int mi = 0; mi < 2; mi++) {
        float c[8][4];
#pragma unroll
        for (int nj = 0; nj < 8; nj++) {
            const float b0 = bias[n0 + wn*64 + nj*8 + qc];
            const float b1 = bias[n0 + wn*64 + nj*8 + qc + 1];
            c[nj][0] = acc[mi][nj][0] + b0;
            c[nj][1] = acc[mi][nj][1] + b1;
            c[nj][2] = acc[mi][nj][2] + b0;
            c[nj][3] = acc[mi][nj][3] + b1;
        }
        if (norm) {
            float ss0 = 0.f, ss1 = 0.f;
#pragma unroll
            for (int nj = 0; nj < 8; nj++) {
                ss0 += c[nj][0]*c[nj][0] + c[nj][1]*c[nj][1];
                ss1 += c[nj][2]*c[nj][2] + c[nj][3]*c[nj][3];
            }
            ss0 += __shfl_xor_sync(0xffffffffu, ss0, 1);
            ss0 += __shfl_xor_sync(0xffffffffu, ss0, 2);
            ss1 += __shfl_xor_sync(0xffffffffu, ss1, 1);
            ss1 += __shfl_xor_sync(0xffffffffu, ss1, 2);
            const float inv0 = 1.0f / fmaxf(sqrtf(ss0), 1e-12f);
            const float inv1 = 1.0f / fmaxf(sqrtf(ss1), 1e-12f);
#pragma unroll
            for (int nj = 0; nj < 8; nj++) {
                c[nj][0] *= inv0; c[nj][1] *= inv0;
                c[nj][2] *= inv1; c[nj][3] *= inv1;
            }
        }
        const int row_lo = m0 + wm*32 + mi*16 + qr;
#pragma unroll
        for (int nj = 0; nj < 8; nj++) {
            const int col = n0 + wn*64 + nj*8 + qc;
            float2 lo; lo.x = c[nj][0]; lo.y = c[nj][1];
            float2 hi; hi.x = c[nj][2]; hi.y = c[nj][3];
            *(float2*)(C + (size_t)row_lo       * N + col) = lo;
            *(float2*)(C + (size_t)(row_lo + 8) * N + col) = hi;
        }
    }
}

__global__ __launch_bounds__(256, 2) void gemm_bf16_qkv_kernel(
    const float* __restrict__ bq, const float* __restrict__ bk,
    const float* __restrict__ bv)
{
    const int z = blockIdx.z;
    const __nv_bfloat16* Wh = g_Whi + (size_t)z*HIDDEN*HIDDEN;
    const __nv_bfloat16* Wl = g_Wlo + (size_t)z*HIDDEN*HIDDEN;
    const float* bias; float* out; bool norm;
    if (z == 0)      { bias = bq; out = g_q; norm = true;  }
    else if (z == 1) { bias = bk; out = g_k; norm = true;  }
    else             { bias = bv; out = g_v; norm = false; }
    gemm_bf16_body(g_Xhi, g_Xlo, Wh, Wl, bias, out,
                   blockIdx.y * 128, blockIdx.x * 128, norm);
}

__global__ __launch_bounds__(256, 2) void gemm_bf16_out_kernel(
    const float* __restrict__ bo, float* __restrict__ C)
{
    gemm_bf16_body(g_Ohi, g_Olo,
                   g_Whi + (size_t)3*HIDDEN*HIDDEN,
                   g_Wlo + (size_t)3*HIDDEN*HIDDEN,
                   bo, C, blockIdx.y * 128, blockIdx.x * 128, false);
}

// ---------------------------------------------------------------------------
// Sequential delta-rule scan (R8 schedule); o written pre-split as bf16 hi/lo.
// ---------------------------------------------------------------------------
__device__ __forceinline__ float clip1(float x) {
    return fminf(fmaxf(x, -CLAMP_F), CLAMP_F);
}

__global__ __launch_bounds__(128) void scan_kernel(float* __restrict__ state_out)
{
    __shared__ float Ssh[HEAD_DIM][68];
    __shared__ float ksh[2][HEAD_DIM];
    __shared__ float qsh[2][HEAD_DIM];
    __shared__ float pd[2][HEAD_DIM];
    __shared__ float po[2][HEAD_DIM];

    const int tid = threadIdx.x;
    const int t   = tid & 63;
    const int g   = tid >> 6;
    const int rb  = g * 32;
    const int bh  = blockIdx.x;
    const size_t base = (size_t)(bh >> 4) * SEQ * HIDDEN
                      + (size_t)(bh & 15) * HEAD_DIM + t;

    float S[32];
#pragma unroll
    for (int i = 0; i < 32; i++) S[i] = 0.f;

    if (g == 0) ksh[0][t] = g_k[base];
    else        qsh[0][t] = g_q[base];
    float kA = (g == 0) ? g_k[base + HIDDEN] : g_q[base + HIDDEN];
    float kB = 0.f;
    float vC = g_v[base];
    float vA = g_v[base + HIDDEN];
    float vB = 0.f;
    float voldraw = 0.f;
    float p = 1.f;
    __syncthreads();

    for (int s = 0; s < SEQ; s++) {
        const int cur = s & 1;
        const int nxt = cur ^ 1;

        if (s + 2 < SEQ) {
            const size_t b2 = base + (size_t)(s + 2) * HIDDEN;
            kB = (g == 0) ? g_k[b2] : g_q[b2];
            vB = g_v[b2];
        }

        const float bd = BETA_F * clip1(vC - p * voldraw);
        float lmax = 0.f;
        {
            const float4* kc = (const float4*)&ksh[cur][rb];
            if (p == 1.f) {
#pragma unroll
                for (int c = 0; c < 8; c++) {
                    const float4 k4 = kc[c];
                    float x0=fmaf(bd,k4.x,S[c*4+0]), x1=fmaf(bd,k4.y,S[c*4+1]);
                    float x2=fmaf(bd,k4.z,S[c*4+2]), x3=fmaf(bd,k4.w,S[c*4+3]);
                    S[c*4+0]=x0; S[c*4+1]=x1; S[c*4+2]=x2; S[c*4+3]=x3;
                    lmax = fmaxf(lmax, fmaxf(fmaxf(fabsf(x0),fabsf(x1)),
                                             fmaxf(fabsf(x2),fabsf(x3))));
                }
            } else {
#pragma unroll
                for (int c = 0; c < 8; c++) {
                    const float4 k4 = kc[c];
                    float x0=fmaf(p,S[c*4+0],bd*k4.x), x1=fmaf(p,S[c*4+1],bd*k4.y);
                    float x2=fmaf(p,S[c*4+2],bd*k4.z), x3=fmaf(p,S[c*4+3],bd*k4.w);
                    S[c*4+0]=x0; S[c*4+1]=x1; S[c*4+2]=x2; S[c*4+3]=x3;
                    lmax = fmaxf(lmax, fmaxf(fmaxf(fabsf(x0),fabsf(x1)),
                                             fmaxf(fabsf(x2),fabsf(x3))));
                }
            }
        }
#pragma unroll
        for (int i = 0; i < 32; i++) Ssh[rb + i][t] = S[i];
        if (s + 1 < SEQ) {
            if (g == 0) ksh[nxt][t] = kA; else qsh[nxt][t] = kA;
        }

        const int over = __syncthreads_or(lmax > STATE_CAP_F);       // barA
        const float pn = over ? 0.9f : 1.0f;

        {
            const float4* qc = (const float4*)&qsh[cur][rb];
            const float4* sr = (const float4*)&Ssh[t][rb];
            float o0=0.f,o1=0.f,o2=0.f,o3=0.f;
#pragma unroll
            for (int c = 0; c < 8; c++) {
                const float4 q4 = qc[c]; const float4 s4 = sr[c];
                o0 += s4.x*q4.x; o1 += s4.y*q4.y;
                o2 += s4.z*q4.z; o3 += s4.w*q4.w;
            }
            po[g][t] = (o0+o1)+(o2+o3);
        }
        if (s + 1 < SEQ) {
            const float4* kn = (const float4*)&ksh[nxt][rb];
            float d0=0.f,d1=0.f,d2=0.f,d3=0.f;
#pragma unroll
            for (int c = 0; c < 8; c++) {
                const float4 k4 = kn[c];
                d0 += k4.x*S[c*4+0]; d1 += k4.y*S[c*4+1];
                d2 += k4.z*S[c*4+2]; d3 += k4.w*S[c*4+3];
            }
            pd[g][t] = (d0+d1)+(d2+d3);
        }
        __syncthreads();                                             // barB

        if (g == 0) {
            const float val = clip1(pn * (po[0][t] + po[1][t]));
            __nv_bfloat16 h, l;
            bf16_split1(val, h, l);
            const size_t idx = base + (size_t)s * HIDDEN;
            g_Ohi[idx] = h; g_Olo[idx] = l;
        }
        voldraw = pd[0][t] + pd[1][t];
        p  = pn;
        vC = vA; vA = vB; kA = kB;
    }

    float* sp = state_out + (size_t)bh * HEAD_DIM * HEAD_DIM;
#pragma unroll
    for (int i = 0; i < 32; i++)
        sp[(rb + i) * HEAD_DIM + t] = p * S[i];
}

// ---------------------------------------------------------------------------
extern "C" void kernel_launch(void* const* d_in, const int* in_sizes, int n_in,
                              void* d_out, int out_size)
{
    (void)in_sizes; (void)n_in;
    const float* x  = (const float*)d_in[0];
    const float* Wq = (const float*)d_in[1];
    const float* bq = (const float*)d_in[2];
    const float* Wk = (const float*)d_in[3];
    const float* bk = (const float*)d_in[4];
    const float* Wv = (const float*)d_in[5];
    const float* bv = (const float*)d_in[6];
    const float* Wo = (const float*)d_in[7];
    const float* bo = (const float*)d_in[8];

    const int OUT_ELEMS   = ROWS * HIDDEN;
    const int STATE_ELEMS = BATCH * HEADS * HEAD_DIM * HEAD_DIM;

    float* state_out;
    if (out_size >= OUT_ELEMS + STATE_ELEMS) {
        state_out = (float*)d_out + OUT_ELEMS;
    } else {
        cudaGetSymbolAddress((void**)&state_out, g_state_scratch);
    }

    static bool attr_done = false;
    if (!attr_done) {
        cudaFuncSetAttribute(gemm_bf16_qkv_kernel,
                             cudaFuncAttributeMaxDynamicSharedMemorySize,
                             SMEM_TOTAL_B);
        cudaFuncSetAttribute(gemm_bf16_out_kernel,
                             cudaFuncAttributeMaxDynamicSharedMemorySize,
                             SMEM_TOTAL_B);
        attr_done = true;
    }

    // 0) pre-split X and all four weights to bf16 hi/lo
    dim3 gs(ROWS * HIDDEN / 8 / 256, 1, 5);
    split_kernel<<<gs, 256>>>(x, Wq, Wk, Wv, Wo);

    // 1) QKV projections (tensor-core bf16x3, cp.async, 2 CTAs/SM) + norm
    dim3 gq(HIDDEN / 128, ROWS / 128, 3);
    gemm_bf16_qkv_kernel<<<gq, 256, SMEM_TOTAL_B>>>(bq, bk, bv);

    // 2) sequential delta-rule scan (writes o pre-split to bf16 hi/lo)
    scan_kernel<<<BATCH * HEADS, 128>>>(state_out);

    // 3) output projection -> d_out
    dim3 go(HIDDEN / 128, ROWS / 128);
    gemm_bf16_out_kernel<<<go, 256, SMEM_TOTAL_B>>>(bo, (float*)d_out);
}

// round 12
// speedup vs baseline: 2.0577x; 1.0437x over previous
#include <cuda_runtime.h>
#include <cuda_bf16.h>
#include <cstdint>

#define HIDDEN    1024
#define HEADS     16
#define HEAD_DIM  64
#define BATCH     4
#define SEQ       1024
#define ROWS      (BATCH*SEQ)        // 4096
#define BETA_F    0.9f
#define CLAMP_F   1.0f
#define STATE_CAP_F 10.0f
#define PITCH     40                 // ushorts per smem row (80 B, bank-clean)

#define ARR_BYTES    (128*PITCH*2)   // 10240
#define STAGE_BYTES  (4*ARR_BYTES)   // 40960
#define SMEM_TOTAL_B (2*STAGE_BYTES) // 81920

// ---------------- scratch (static device arrays are allowed) ---------------
__device__ float g_q[ROWS*HIDDEN];
__device__ float g_k[ROWS*HIDDEN];
__device__ float g_v[ROWS*HIDDEN];
__device__ float g_state_scratch[BATCH*HEADS*HEAD_DIM*HEAD_DIM];

// pre-split bf16 operands
__device__ __nv_bfloat16 g_Xhi[ROWS*HIDDEN],  g_Xlo[ROWS*HIDDEN];
__device__ __nv_bfloat16 g_Whi[4*HIDDEN*HIDDEN], g_Wlo[4*HIDDEN*HIDDEN]; // q,k,v,o
__device__ __nv_bfloat16 g_Ohi[ROWS*HIDDEN],  g_Olo[ROWS*HIDDEN];

// ---------------------------------------------------------------------------
#define MMA16816(d, a, b0, b1)                                              \
    asm volatile("mma.sync.aligned.m16n8k16.row.col.f32.bf16.bf16.f32 "     \
                 "{%0,%1,%2,%3}, {%4,%5,%6,%7}, {%8,%9}, {%0,%1,%2,%3};"    \
                 : "+f"((d)[0]), "+f"((d)[1]), "+f"((d)[2]), "+f"((d)[3])   \
                 : "r"((a)[0]), "r"((a)[1]), "r"((a)[2]), "r"((a)[3]),      \
                   "r"(b0), "r"(b1))

#define LDSM4(r, addr)                                                      \
    asm volatile("ldmatrix.sync.aligned.m8n8.x4.shared.b16 "                \
                 "{%0,%1,%2,%3}, [%4];"                                     \
                 : "=r"((r)[0]), "=r"((r)[1]), "=r"((r)[2]), "=r"((r)[3])   \
                 : "r"(addr))

#define CP16(dst, src)                                                      \
    asm volatile("cp.async.cg.shared.global [%0], [%1], 16;"                \
                 :: "r"(dst), "l"(src))
#define CP_COMMIT() asm volatile("cp.async.commit_group;")
#define CP_WAIT(n)  asm volatile("cp.async.wait_group %0;" :: "n"(n))

__device__ __forceinline__ void bf16_split1(float x, __nv_bfloat16& h,
                                            __nv_bfloat16& l)
{
    h = __float2bfloat16_rn(x);
    l = __float2bfloat16_rn(x - __bfloat162float(h));
}

// ---------------------------------------------------------------------------
// split fp32 -> bf16 hi/lo. z=0: X; z=1..4: Wq,Wk,Wv,Wo. 8 elems/thread.
// ---------------------------------------------------------------------------
__global__ __launch_bounds__(256) void split_kernel(
    const float* __restrict__ X,  const float* __restrict__ Wq,
    const float* __restrict__ Wk, const float* __restrict__ Wv,
    const float* __restrict__ Wo)
{
    const int z = blockIdx.z;
    const float* src; __nv_bfloat16* hi; __nv_bfloat16* lo; int n8;
    if (z == 0) { src = X;  hi = g_Xhi; lo = g_Xlo; n8 = ROWS*HIDDEN/8; }
    else {
        const float* ws[4] = {Wq, Wk, Wv, Wo};
        src = ws[z-1];
        hi = g_Whi + (size_t)(z-1)*HIDDEN*HIDDEN;
        lo = g_Wlo + (size_t)(z-1)*HIDDEN*HIDDEN;
        n8 = HIDDEN*HIDDEN/8;
    }
    const int i = blockIdx.x * 256 + threadIdx.x;
    if (i >= n8) return;
    const float4* p = (const float4*)src + 2*(size_t)i;
    float4 x0 = p[0], x1 = p[1];
    __nv_bfloat16 h[8], l[8];
    bf16_split1(x0.x, h[0], l[0]); bf16_split1(x0.y, h[1], l[1]);
    bf16_split1(x0.z, h[2], l[2]); bf16_split1(x0.w, h[3], l[3]);
    bf16_split1(x1.x, h[4], l[4]); bf16_split1(x1.y, h[5], l[5]);
    bf16_split1(x1.z, h[6], l[6]); bf16_split1(x1.w, h[7], l[7]);
    *(uint4*)(hi + 8*(size_t)i) = *(uint4*)h;
    *(uint4*)(lo + 8*(size_t)i) = *(uint4*)l;
}

// ---------------------------------------------------------------------------
// bf16x3 tensor-core GEMM (unchanged from R11).
// ---------------------------------------------------------------------------
__device__ __forceinline__ void gemm_bf16_body(
    const __nv_bfloat16* __restrict__ Ahi, const __nv_bfloat16* __restrict__ Alo,
    const __nv_bfloat16* __restrict__ Bhi, const __nv_bfloat16* __restrict__ Blo,
    const float* __restrict__ bias, float* __restrict__ C,
    int m0, int n0, bool norm)
{
    extern __shared__ unsigned short dynsm[];
    const int N = HIDDEN, K = HIDDEN;

    const int tid  = threadIdx.x;
    const int lane = tid & 31;
    const int warp = tid >> 5;
    const int wm   = warp & 3;
    const int wn   = warp >> 2;

    const int arow = tid >> 1;
    const int acol = (tid & 1) * 16;
    const size_t aoff0 = (size_t)(m0 + arow) * K + acol;
    const size_t boff0 = (size_t)(n0 + arow) * K + acol;
    const uint32_t smbase = (uint32_t)__cvta_generic_to_shared(dynsm);
    const uint32_t dst0   = smbase + (uint32_t)(arow * (PITCH*2) + (tid & 1) * 32);

    const int a_row_l = lane & 15;
    const int a_col_l = (lane >> 4) << 3;
    const int b_n_l   = ((lane >> 4) << 3) + (lane & 7);
    const int b_k_l   = ((lane >> 3) & 1) << 3;

    float acc[2][8][4];
#pragma unroll
    for (int mi = 0; mi < 2; mi++)
#pragma unroll
        for (int nj = 0; nj < 8; nj++)
#pragma unroll
            for (int r = 0; r < 4; r++) acc[mi][nj][r] = 0.f;

    {
        const uint32_t d = dst0;
        CP16(d + 0*ARR_BYTES,      Ahi + aoff0);
        CP16(d + 0*ARR_BYTES + 16, Ahi + aoff0 + 8);
        CP16(d + 1*ARR_BYTES,      Alo + aoff0);
        CP16(d + 1*ARR_BYTES + 16, Alo + aoff0 + 8);
        CP16(d + 2*ARR_BYTES,      Bhi + boff0);
        CP16(d + 2*ARR_BYTES + 16, Bhi + boff0 + 8);
        CP16(d + 3*ARR_BYTES,      Blo + boff0);
        CP16(d + 3*ARR_BYTES + 16, Blo + boff0 + 8);
        CP_COMMIT();
    }

    const int NT = K / 32;
    for (int it = 0; it < NT; it++) {
        const int cur = it & 1;
        const int nxt = cur ^ 1;
        const bool hn = (it + 1) < NT;

        if (hn) {
            const int k1 = (it + 1) * 32;
            const uint32_t d = dst0 + nxt * STAGE_BYTES;
            const size_t ao = aoff0 + k1;
            const size_t bo = boff0 + k1;
            CP16(d + 0*ARR_BYTES,      Ahi + ao);
            CP16(d + 0*ARR_BYTES + 16, Ahi + ao + 8);
            CP16(d + 1*ARR_BYTES,      Alo + ao);
            CP16(d + 1*ARR_BYTES + 16, Alo + ao + 8);
            CP16(d + 2*ARR_BYTES,      Bhi + bo);
            CP16(d + 2*ARR_BYTES + 16, Bhi + bo + 8);
            CP16(d + 3*ARR_BYTES,      Blo + bo);
            CP16(d + 3*ARR_BYTES + 16, Blo + bo + 8);
            CP_COMMIT();
            CP_WAIT(1);
        } else {
            CP_WAIT(0);
        }
        __syncthreads();

        const uint32_t stA_hi = smbase + cur*STAGE_BYTES + 0*ARR_BYTES;
        const uint32_t stA_lo = smbase + cur*STAGE_BYTES + 1*ARR_BYTES;
        const uint32_t stB_hi = smbase + cur*STAGE_BYTES + 2*ARR_BYTES;
        const uint32_t stB_lo = smbase + cur*STAGE_BYTES + 3*ARR_BYTES;

#pragma unroll
        for (int ks = 0; ks < 2; ks++) {
            const int koff = ks * 16;
            uint32_t afh[2][4], afl[2][4];
#pragma unroll
            for (int mi = 0; mi < 2; mi++) {
                const uint32_t off =
                    ((uint32_t)((wm*32 + mi*16 + a_row_l) * PITCH
                                + koff + a_col_l)) * 2u;
                LDSM4(afh[mi], stA_hi + off);
                LDSM4(afl[mi], stA_lo + off);
            }
#pragma unroll
            for (int jp = 0; jp < 4; jp++) {
                uint32_t bfh[4], bfl[4];
                const uint32_t off =
                    ((uint32_t)((wn*64 + jp*16 + b_n_l) * PITCH
                                + koff + b_k_l)) * 2u;
                LDSM4(bfh, stB_hi + off);
                LDSM4(bfl, stB_lo + off);
#pragma unroll
                for (int mi = 0; mi < 2; mi++) {
                    MMA16816(acc[mi][2*jp],   afh[mi], bfh[0], bfh[1]);
                    MMA16816(acc[mi][2*jp],   afh[mi], bfl[0], bfl[1]);
                    MMA16816(acc[mi][2*jp],   afl[mi], bfh[0], bfh[1]);
                    MMA16816(acc[mi][2*jp+1], afh[mi], bfh[2], bfh[3]);
                    MMA16816(acc[mi][2*jp+1], afh[mi], bfl[2], bfl[3]);
                    MMA16816(acc[mi][2*jp+1], afl[mi], bfh[2], bfh[3]);
                }
            }
        }
        __syncthreads();
    }

    const int qr = lane >> 2;
    const int qc = (lane & 3) * 2;

#pragma unroll
    for (int mi = 0; mi < 2; mi++) {
        float c[8][4];
#pragma unroll
        for (int nj = 0; nj < 8; nj++) {
            const float b0 = bias[n0 + wn*64 + nj*8 + qc];
            const float b1 = bias[n0 + wn*64 + nj*8 + qc + 1];
            c[nj][0] = acc[mi][nj][0] + b0;
            c[nj][1] = acc[mi][nj][1] + b1;
            c[nj][2] = acc[mi][nj][2] + b0;
            c[nj][3] = acc[mi][nj][3] + b1;
        }
        if (norm) {
            float ss0 = 0.f, ss1 = 0.f;
#pragma unroll
            for (int nj = 0; nj < 8; nj++) {
                ss0 += c[nj][0]*c[nj][0] + c[nj][1]*c[nj][1];
                ss1 += c[nj][2]*c[nj][2] + c[nj][3]*c[nj][3];
            }
            ss0 += __shfl_xor_sync(0xffffffffu, ss0, 1);
            ss0 += __shfl_xor_sync(0xffffffffu, ss0, 2);
            ss1 += __shfl_xor_sync(0xffffffffu, ss1, 1);
            ss1 += __shfl_xor_sync(0xffffffffu, ss1, 2);
            const float inv0 = 1.0f / fmaxf(sqrtf(ss0), 1e-12f);
            const float inv1 = 1.0f / fmaxf(sqrtf(ss1), 1e-12f);
#pragma unroll
            for (int nj = 0; nj < 8; nj++) {
                c[nj][0] *= inv0; c[nj][1] *= inv0;
                c[nj][2] *= inv1; c[nj][3] *= inv1;
            }
        }
        const int row_lo = m0 + wm*32 + mi*16 + qr;
#pragma unroll
        for (int nj = 0; nj < 8; nj++) {
            const int col = n0 + wn*64 + nj*8 + qc;
            float2 lo; lo.x = c[nj][0]; lo.y = c[nj][1];
            float2 hi; hi.x = c[nj][2]; hi.y = c[nj][3];
            *(float2*)(C + (size_t)row_lo       * N + col) = lo;
            *(float2*)(C + (size_t)(row_lo + 8) * N + col) = hi;
        }
    }
}

__global__ __launch_bounds__(256, 2) void gemm_bf16_qkv_kernel(
    const float* __restrict__ bq, const float* __restrict__ bk,
    const float* __restrict__ bv)
{
    const int z = blockIdx.z;
    const __nv_bfloat16* Wh = g_Whi + (size_t)z*HIDDEN*HIDDEN;
    const __nv_bfloat16* Wl = g_Wlo + (size_t)z*HIDDEN*HIDDEN;
    const float* bias; float* out; bool norm;
    if (z == 0)      { bias = bq; out = g_q; norm = true;  }
    else if (z == 1) { bias = bk; out = g_k; norm = true;  }
    else             { bias = bv; out = g_v; norm = false; }
    gemm_bf16_body(g_Xhi, g_Xlo, Wh, Wl, bias, out,
                   blockIdx.y * 128, blockIdx.x * 128, norm);
}

__global__ __launch_bounds__(256, 2) void gemm_bf16_out_kernel(
    const float* __restrict__ bo, float* __restrict__ C)
{
    gemm_bf16_body(g_Ohi, g_Olo,
                   g_Whi + (size_t)3*HIDDEN*HIDDEN,
                   g_Wlo + (size_t)3*HIDDEN*HIDDEN,
                   bo, C, blockIdx.y * 128, blockIdx.x * 128, false);
}

// ---------------------------------------------------------------------------
// Sequential delta-rule scan, dual-orientation register state.
// One 128-thread block per (b,h). Thread (t,g): t=0..63, g=row/col half.
//   Sc[i] = S[g*32+i][t]   (column copy — drives the recursion)
//   Sr[j] = S[t][g*32+j]   (row copy    — drives the o-dot)
// True state = p * raw copies (lazy 0.9 fold). Bit-identical updates on both
// copies (products commute exactly). No full-state shared publish: per-step
// shared traffic is k/q/delta (64 floats each) + 2x64 partials.
// Schedule:
//   top : prefetch gmem step s+2
//   preA: bd; dsh[t]=bd; column update (p*Sc + bd*k) + lmax; stage k/q[nxt]
//   barA: __syncthreads_or(lmax > cap) -> pn    (also publishes dsh)
//   postA: row update (p*Sr + k[t]*dsh); po = Sr . q_s; pd = k_{s+1} . Sc
//   barB; tail: o_s = clip(pn*(po0+po1)); voldraw = pd0+pd1; roll
// ---------------------------------------------------------------------------
__device__ __forceinline__ float clip1(float x) {
    return fminf(fmaxf(x, -CLAMP_F), CLAMP_F);
}

__global__ __launch_bounds__(128) void scan_kernel(float* __restrict__ state_out)
{
    __shared__ float ksh[2][HEAD_DIM];
    __shared__ float qsh[2][HEAD_DIM];
    __shared__ float dsh[HEAD_DIM];
    __shared__ float pd[2][HEAD_DIM];
    __shared__ float po[2][HEAD_DIM];

    const int tid = threadIdx.x;
    const int t   = tid & 63;
    const int g   = tid >> 6;
    const int rb  = g * 32;
    const int bh  = blockIdx.x;
    const size_t base = (size_t)(bh >> 4) * SEQ * HIDDEN
                      + (size_t)(bh & 15) * HEAD_DIM + t;

    float Sc[32], Sr[32];
#pragma unroll
    for (int i = 0; i < 32; i++) { Sc[i] = 0.f; Sr[i] = 0.f; }

    if (g == 0) ksh[0][t] = g_k[base];
    else        qsh[0][t] = g_q[base];
    float kA = (g == 0) ? g_k[base + HIDDEN] : g_q[base + HIDDEN];
    float kB = 0.f;
    float vC = g_v[base];
    float vA = g_v[base + HIDDEN];
    float vB = 0.f;
    float voldraw = 0.f;
    float p = 1.f;
    __syncthreads();

    for (int s = 0; s < SEQ; s++) {
        const int cur = s & 1;
        const int nxt = cur ^ 1;

        // prefetch step s+2 (full step of latency cover)
        if (s + 2 < SEQ) {
            const size_t b2 = base + (size_t)(s + 2) * HIDDEN;
            kB = (g == 0) ? g_k[b2] : g_q[b2];
            vB = g_v[b2];
        }

        // preA: bd, share delta, column update + lmax, stage next k/q
        const float bd = BETA_F * clip1(vC - p * voldraw);
        if (g == 0) dsh[t] = bd;
        float lmax = 0.f;
        {
            const float4* kc = (const float4*)&ksh[cur][rb];
            if (p == 1.f) {
#pragma unroll
                for (int c = 0; c < 8; c++) {
                    const float4 k4 = kc[c];
                    float x0=fmaf(bd,k4.x,Sc[c*4+0]), x1=fmaf(bd,k4.y,Sc[c*4+1]);
                    float x2=fmaf(bd,k4.z,Sc[c*4+2]), x3=fmaf(bd,k4.w,Sc[c*4+3]);
                    Sc[c*4+0]=x0; Sc[c*4+1]=x1; Sc[c*4+2]=x2; Sc[c*4+3]=x3;
                    lmax = fmaxf(lmax, fmaxf(fmaxf(fabsf(x0),fabsf(x1)),
                                             fmaxf(fabsf(x2),fabsf(x3))));
                }
            } else {
#pragma unroll
                for (int c = 0; c < 8; c++) {
                    const float4 k4 = kc[c];
                    float x0=fmaf(p,Sc[c*4+0],bd*k4.x), x1=fmaf(p,Sc[c*4+1],bd*k4.y);
                    float x2=fmaf(p,Sc[c*4+2],bd*k4.z), x3=fmaf(p,Sc[c*4+3],bd*k4.w);
                    Sc[c*4+0]=x0; Sc[c*4+1]=x1; Sc[c*4+2]=x2; Sc[c*4+3]=x3;
                    lmax = fmaxf(lmax, fmaxf(fmaxf(fabsf(x0),fabsf(x1)),
                                             fmaxf(fabsf(x2),fabsf(x3))));
                }
            }
        }
        if (s + 1 < SEQ) {
            if (g == 0) ksh[nxt][t] = kA; else qsh[nxt][t] = kA;
        }

        const int over = __syncthreads_or(lmax > STATE_CAP_F);       // barA
        const float pn = over ? 0.9f : 1.0f;

        // postA: row update from shared delta, then o partial from row copy
        {
            const float kt = ksh[cur][t];
            const float4* d4 = (const float4*)&dsh[rb];
            const float4* qc = (const float4*)&qsh[cur][rb];
            float o0=0.f,o1=0.f,o2=0.f,o3=0.f;
            if (p == 1.f) {
#pragma unroll
                for (int c = 0; c < 8; c++) {
                    const float4 dd = d4[c];
                    float y0=fmaf(kt,dd.x,Sr[c*4+0]), y1=fmaf(kt,dd.y,Sr[c*4+1]);
                    float y2=fmaf(kt,dd.z,Sr[c*4+2]), y3=fmaf(kt,dd.w,Sr[c*4+3]);
                    Sr[c*4+0]=y0; Sr[c*4+1]=y1; Sr[c*4+2]=y2; Sr[c*4+3]=y3;
                    const float4 q4 = qc[c];
                    o0 += y0*q4.x; o1 += y1*q4.y;
                    o2 += y2*q4.z; o3 += y3*q4.w;
                }
            } else {
#pragma unroll
                for (int c = 0; c < 8; c++) {
                    const float4 dd = d4[c];
                    float y0=fmaf(p,Sr[c*4+0],kt*dd.x), y1=fmaf(p,Sr[c*4+1],kt*dd.y);
                    float y2=fmaf(p,Sr[c*4+2],kt*dd.z), y3=fmaf(p,Sr[c*4+3],kt*dd.w);
                    Sr[c*4+0]=y0; Sr[c*4+1]=y1; Sr[c*4+2]=y2; Sr[c*4+3]=y3;
                    const float4 q4 = qc[c];
                    o0 += y0*q4.x; o1 += y1*q4.y;
                    o2 += y2*q4.z; o3 += y3*q4.w;
                }
            }
            po[g][t] = (o0+o1)+(o2+o3);
        }
        // pd partial for step s+1 from the column copy
        if (s + 1 < SEQ) {
            const float4* kn = (const float4*)&ksh[nxt][rb];
            float d0=0.f,d1=0.f,d2=0.f,d3=0.f;
#pragma unroll
            for (int c = 0; c < 8; c++) {
                const float4 k4 = kn[c];
                d0 += k4.x*Sc[c*4+0]; d1 += k4.y*Sc[c*4+1];
                d2 += k4.z*Sc[c*4+2]; d3 += k4.w*Sc[c*4+3];
            }
            pd[g][t] = (d0+d1)+(d2+d3);
        }
        __syncthreads();                                             // barB

        if (g == 0) {
            const float val = clip1(pn * (po[0][t] + po[1][t]));
            __nv_bfloat16 h, l;
            bf16_split1(val, h, l);
            const size_t idx = base + (size_t)s * HIDDEN;
            g_Ohi[idx] = h; g_Olo[idx] = l;
        }
        voldraw = pd[0][t] + pd[1][t];
        p  = pn;
        vC = vA; vA = vB; kA = kB;
    }

    // final true state = p * raw column copy : state_out[b][h][d][e]
    float* sp = state_out + (size_t)bh * HEAD_DIM * HEAD_DIM;
#pragma unroll
    for (int i = 0; i < 32; i++)
        sp[(rb + i) * HEAD_DIM + t] = p * Sc[i];
}

// ---------------------------------------------------------------------------
extern "C" void kernel_launch(void* const* d_in, const int* in_sizes, int n_in,
                              void* d_out, int out_size)
{
    (void)in_sizes; (void)n_in;
    const float* x  = (const float*)d_in[0];
    const float* Wq = (const float*)d_in[1];
    const float* bq = (const float*)d_in[2];
    const float* Wk = (const float*)d_in[3];
    const float* bk = (const float*)d_in[4];
    const float* Wv = (const float*)d_in[5];
    const float* bv = (const float*)d_in[6];
    const float* Wo = (const float*)d_in[7];
    const float* bo = (const float*)d_in[8];

    const int OUT_ELEMS   = ROWS * HIDDEN;
    const int STATE_ELEMS = BATCH * HEADS * HEAD_DIM * HEAD_DIM;

    float* state_out;
    if (out_size >= OUT_ELEMS + STATE_ELEMS) {
        state_out = (float*)d_out + OUT_ELEMS;
    } else {
        cudaGetSymbolAddress((void**)&state_out, g_state_scratch);
    }

    static bool attr_done = false;
    if (!attr_done) {
        cudaFuncSetAttribute(gemm_bf16_qkv_kernel,
                             cudaFuncAttributeMaxDynamicSharedMemorySize,
                             SMEM_TOTAL_B);
        cudaFuncSetAttribute(gemm_bf16_out_kernel,
                             cudaFuncAttributeMaxDynamicSharedMemorySize,
                             SMEM_TOTAL_B);
        attr_done = true;
    }

    // 0) pre-split X and all four weights to bf16 hi/lo
    dim3 gs(ROWS * HIDDEN / 8 / 256, 1, 5);
    split_kernel<<<gs, 256>>>(x, Wq, Wk, Wv, Wo);

    // 1) QKV projections (tensor-core bf16x3, cp.async, 2 CTAs/SM) + norm
    dim3 gq(HIDDEN / 128, ROWS / 128, 3);
    gemm_bf16_qkv_kernel<<<gq, 256, SMEM_TOTAL_B>>>(bq, bk, bv);

    // 2) sequential delta-rule scan (dual-orientation register state)
    scan_kernel<<<BATCH * HEADS, 128>>>(state_out);

    // 3) output projection -> d_out
    dim3 go(HIDDEN / 128, ROWS / 128);
    gemm_bf16_out_kernel<<<go, 256, SMEM_TOTAL_B>>>(bo, (float*)d_out);
}